// round 5
// baseline (speedup 1.0000x reference)
#include <cuda_runtime.h>
#include <cuda_fp16.h>
#include <cstdint>

// Problem constants
#define BATCH 8
#define HH 96
#define WW 96
#define CC 128
#define LL (HH*WW)            // 9216
#define ROWS (BATCH*LL)       // 73728
#define NWIN 144
#define WS 8
#define NTOK 64
#define HEADS 4
#define HD 32
#define QKSCALE 0.17677669529663687f

// ---------------- scratch -----------------
__device__ __half g_xw [ (size_t)ROWS*CC ];
__device__ __half g_qkv[ (size_t)ROWS*3*CC ];
__device__ __half g_att[ (size_t)ROWS*CC ];
__device__ float  g_xa [ (size_t)ROWS*CC ];
__device__ float  g_xb [ (size_t)ROWS*CC ];
__device__ __half g_h  [ (size_t)ROWS*4*CC ];
__device__ __half g_wt [ 524288 ];

__device__ __forceinline__ uint32_t smem_u32(const void* p) {
    uint32_t a;
    asm("{ .reg .u64 t; cvta.to.shared.u64 t, %1; cvt.u32.u64 %0, t; }" : "=r"(a) : "l"(p));
    return a;
}
__device__ __forceinline__ float gelu_exact(float x) {
    return 0.5f * x * (1.f + erff(x * 0.70710678118654752f));
}
__device__ __forceinline__ uint2 f4_to_h4(float4 v) {
    union { uint2 u; __half2 h[2]; } cv;
    cv.h[0] = __floats2half2_rn(v.x, v.y);
    cv.h[1] = __floats2half2_rn(v.z, v.w);
    return cv.u;
}

#define LDSM4(r, addr) \
    asm volatile("ldmatrix.sync.aligned.m8n8.x4.shared.b16 {%0,%1,%2,%3},[%4];" \
        : "=r"((r)[0]), "=r"((r)[1]), "=r"((r)[2]), "=r"((r)[3]) : "r"(addr))

// ---------------- LayerNorm (+ optional gather), half output ----------------
template<bool GATHER>
__global__ __launch_bounds__(128) void ln_kernel(
    const float* __restrict__ x, const float* __restrict__ gam,
    const float* __restrict__ bet, __half* __restrict__ out, int shift)
{
    int lane = threadIdx.x & 31;
    int warp = threadIdx.x >> 5;
    int r = blockIdx.x * 4 + warp;
    const float* src;
    if (GATHER) {
        int wi = r >> 6, n = r & 63;
        int b  = wi / NWIN, wl = wi % NWIN;
        int whi = wl / 12, wwi = wl % 12;
        int h0 = whi * 8 + (n >> 3), w0 = wwi * 8 + (n & 7);
        int hs = h0 + shift; if (hs >= HH) hs -= HH;
        int ws_ = w0 + shift; if (ws_ >= WW) ws_ -= WW;
        src = &x[(size_t)(b * LL + hs * WW + ws_) * CC];
    } else {
        src = &x[(size_t)r * CC];
    }
    float4 v = *(const float4*)&src[lane * 4];
    float s1 = v.x + v.y + v.z + v.w;
    float s2 = v.x*v.x + v.y*v.y + v.z*v.z + v.w*v.w;
    #pragma unroll
    for (int o = 16; o; o >>= 1) {
        s1 += __shfl_xor_sync(0xffffffffu, s1, o);
        s2 += __shfl_xor_sync(0xffffffffu, s2, o);
    }
    float mean = s1 * (1.f / CC);
    float var  = s2 * (1.f / CC) - mean * mean;
    float rstd = rsqrtf(var + 1e-5f);
    float4 g4 = *(const float4*)&gam[lane * 4];
    float4 b4 = *(const float4*)&bet[lane * 4];
    float4 o4;
    o4.x = (v.x - mean) * rstd * g4.x + b4.x;
    o4.y = (v.y - mean) * rstd * g4.y + b4.y;
    o4.z = (v.z - mean) * rstd * g4.z + b4.z;
    o4.w = (v.w - mean) * rstd * g4.w + b4.w;
    *(uint2*)&out[(size_t)r * CC + lane * 4] = f4_to_h4(o4);
}

// ---------------- batched weight transpose: 9 matrices in one launch --------
struct TPJobs {
    const float* src[9];
    __half* dst[9];
    int K[9];
    int N[9];
};
__global__ __launch_bounds__(256) void transpose_all(TPJobs jb)
{
    __shared__ float t[32][33];
    int m = blockIdx.z;
    int K = jb.K[m], N = jb.N[m];
    int k0 = blockIdx.x * 32, n0 = blockIdx.y * 32;
    if (k0 >= K || n0 >= N) return;
    const float* src = jb.src[m];
    __half* dst = jb.dst[m];
    int x = threadIdx.x & 31, y = threadIdx.x >> 5;
    #pragma unroll
    for (int i = 0; i < 32; i += 8)
        t[y + i][x] = src[(size_t)(k0 + y + i) * N + n0 + x];
    __syncthreads();
    #pragma unroll
    for (int i = 0; i < 32; i += 8)
        dst[(size_t)(n0 + y + i) * K + k0 + x] = __float2half_rn(t[x][y + i]);
}

// ---------------- fp16 mma.sync GEMM (m16n8k16), 3-stage pipeline ------------
#define AS_STRIDE 40
#define TILE_H   (128*AS_STRIDE)           // halves per matrix buffer (5120)
#define NSTAGE   3
#define GM_SMEM  (NSTAGE*2*TILE_H*2)       // 61440 bytes

__device__ __forceinline__ void copy_chunk(
    const __half* __restrict__ A, const __half* __restrict__ B,
    int bm, int bn, int K, int k0, __half* sA, __half* sB, int tid)
{
    uint32_t a_s = smem_u32(sA), b_s = smem_u32(sB);
    #pragma unroll
    for (int i = 0; i < 2; i++) {
        int idx = tid + i * 256;
        int row = idx >> 2, q = idx & 3;
        const __half* ga = &A[(size_t)(bm + row) * K + k0 + q * 8];
        const __half* gb = &B[(size_t)(bn + row) * K + k0 + q * 8];
        uint32_t so = (row * AS_STRIDE + q * 8) * 2;
        asm volatile("cp.async.cg.shared.global [%0],[%1],16;" :: "r"(a_s + so), "l"(ga));
        asm volatile("cp.async.cg.shared.global [%0],[%1],16;" :: "r"(b_s + so), "l"(gb));
    }
    asm volatile("cp.async.commit_group;" ::: "memory");
}

template<int EPI, typename OT>
__global__ __launch_bounds__(256)
void gemm_mma(const __half* __restrict__ A, const __half* __restrict__ B,
              const float* __restrict__ bias, OT* __restrict__ C,
              const float* __restrict__ res, int M, int N, int K, int shift)
{
    extern __shared__ __half smh[];
    int tid = threadIdx.x, lane = tid & 31, wid = tid >> 5;
    int g = lane >> 2, kq = lane & 3;
    int warpM = wid & 3, warpN = wid >> 2;
    int bm = blockIdx.x * 128, bn = blockIdx.y * 128;

    float acc[2][8][4];
    #pragma unroll
    for (int i = 0; i < 2; i++)
        #pragma unroll
        for (int j = 0; j < 8; j++)
            #pragma unroll
            for (int q = 0; q < 4; q++) acc[i][j][q] = 0.f;

    int nc = K >> 5;
    copy_chunk(A, B, bm, bn, K, 0, smh, smh + TILE_H, tid);
    if (nc > 1)
        copy_chunk(A, B, bm, bn, K, 32, smh + 2*TILE_H, smh + 3*TILE_H, tid);

    uint32_t a_off = (((warpM * 32 + (lane & 15)) * AS_STRIDE) + ((lane >> 4) << 3)) * 2;
    uint32_t b_off = (((warpN * 64 + (lane & 7) + (((lane >> 4) & 1) << 3)) * AS_STRIDE)
                     + (((lane >> 3) & 1) << 3)) * 2;

    int st = 0;
    for (int c = 0; c < nc; c++) {
        if (c + 1 < nc)
            asm volatile("cp.async.wait_group 1;" ::: "memory");
        else
            asm volatile("cp.async.wait_group 0;" ::: "memory");
        __syncthreads();
        if (c + 2 < nc) {
            int wst = st + 2; if (wst >= NSTAGE) wst -= NSTAGE;
            copy_chunk(A, B, bm, bn, K, (c + 2) << 5,
                       smh + wst*2*TILE_H, smh + wst*2*TILE_H + TILE_H, tid);
        }

        uint32_t ab = smem_u32(smh + st*2*TILE_H) + a_off;
        uint32_t bb = smem_u32(smh + st*2*TILE_H + TILE_H) + b_off;
        #pragma unroll
        for (int ks = 0; ks < 2; ks++) {
            uint32_t a[2][4], b[4][4];
            LDSM4(a[0], ab + ks * 32);
            LDSM4(a[1], ab + 16 * AS_STRIDE * 2 + ks * 32);
            #pragma unroll
            for (int j16 = 0; j16 < 4; j16++)
                LDSM4(b[j16], bb + j16 * 16 * AS_STRIDE * 2 + ks * 32);
            #pragma unroll
            for (int i = 0; i < 2; i++)
                #pragma unroll
                for (int j = 0; j < 8; j++) {
                    uint32_t b0 = b[j >> 1][(j & 1) * 2];
                    uint32_t b1 = b[j >> 1][(j & 1) * 2 + 1];
                    asm volatile(
                        "mma.sync.aligned.m16n8k16.row.col.f32.f16.f16.f32 "
                        "{%0,%1,%2,%3},{%4,%5,%6,%7},{%8,%9},{%0,%1,%2,%3};"
                        : "+f"(acc[i][j][0]), "+f"(acc[i][j][1]),
                          "+f"(acc[i][j][2]), "+f"(acc[i][j][3])
                        : "r"(a[i][0]), "r"(a[i][1]), "r"(a[i][2]), "r"(a[i][3]),
                          "r"(b0), "r"(b1));
                }
        }
        if (++st == NSTAGE) st = 0;
    }

    #pragma unroll
    for (int i = 0; i < 2; i++) {
        #pragma unroll
        for (int rr = 0; rr < 2; rr++) {
            int gr = bm + warpM * 32 + i * 16 + g + rr * 8;
            int dst = gr;
            if (EPI == 1) {
                int wi = gr >> 6, n = gr & 63;
                int b  = wi / NWIN, wl = wi % NWIN;
                int whi = wl / 12, wwi = wl % 12;
                int h0 = whi * 8 + (n >> 3), w0 = wwi * 8 + (n & 7);
                int h = h0 + shift; if (h >= HH) h -= HH;
                int w = w0 + shift; if (w >= WW) w -= WW;
                dst = b * LL + h * WW + w;
            }
            #pragma unroll
            for (int j = 0; j < 8; j++) {
                int col = bn + warpN * 64 + j * 8 + 2 * kq;
                float vx = acc[i][j][rr*2+0];
                float vy = acc[i][j][rr*2+1];
                if (EPI != 4) {
                    vx += __ldg(&bias[col]);
                    vy += __ldg(&bias[col+1]);
                }
                if (EPI == 2) { vx = gelu_exact(vx); vy = gelu_exact(vy); }
                if (EPI == 1 || EPI == 3) {
                    float2 r2 = *(const float2*)&res[(size_t)dst * N + col];
                    vx += r2.x; vy += r2.y;
                }
                if (sizeof(OT) == 2) {
                    *(__half2*)&((__half*)C)[(size_t)dst * N + col] = __floats2half2_rn(vx, vy);
                } else {
                    *(float2*)&((float*)C)[(size_t)dst * N + col] = make_float2(vx, vy);
                }
            }
        }
    }
}

// ---------------- windowed attention (float4 smem reads) ---------------------
__global__ __launch_bounds__(64) void attn_kernel(
    const __half* __restrict__ qkv, __half* __restrict__ out, int shifted)
{
    __shared__ float k_s[NTOK * HD];
    __shared__ float v_s[NTOK * HD];
    __shared__ int   lab_s[NTOK];
    int wi = blockIdx.x >> 2, head = blockIdx.x & 3, n = threadIdx.x;
    size_t rowbase = (size_t)(wi * NTOK + n) * (3 * CC);
    const __half* krow = &qkv[rowbase + CC     + head * HD];
    const __half* vrow = &qkv[rowbase + 2 * CC + head * HD];
    #pragma unroll
    for (int i = 0; i < 4; i++) {
        union { uint4 u; __half2 h[4]; } ck, cv2;
        ck.u  = *(const uint4*)&krow[i * 8];
        cv2.u = *(const uint4*)&vrow[i * 8];
        #pragma unroll
        for (int p = 0; p < 4; p++) {
            float2 fk = __half22float2(ck.h[p]);
            float2 fv = __half22float2(cv2.h[p]);
            k_s[n * HD + i*8 + p*2]     = fk.x;
            k_s[n * HD + i*8 + p*2 + 1] = fk.y;
            v_s[n * HD + i*8 + p*2]     = fv.x;
            v_s[n * HD + i*8 + p*2 + 1] = fv.y;
        }
    }
    int mylab = 0;
    if (shifted) {
        int wl = wi % NWIN;
        int whi = wl / 12, wwi = wl % 12;
        int h = whi * 8 + (n >> 3), w = wwi * 8 + (n & 7);
        int hr = (h < HH - WS) ? 0 : ((h < HH - 4) ? 1 : 2);
        int wr = (w < WW - WS) ? 0 : ((w < WW - 4) ? 1 : 2);
        mylab = hr * 3 + wr;
        lab_s[n] = mylab;
    }
    float q[HD];
    {
        const __half* qrow = &qkv[rowbase + head * HD];
        #pragma unroll
        for (int i = 0; i < 4; i++) {
            union { uint4 u; __half2 h[4]; } cq;
            cq.u = *(const uint4*)&qrow[i * 8];
            #pragma unroll
            for (int p = 0; p < 4; p++) {
                float2 f = __half22float2(cq.h[p]);
                q[i*8 + p*2]     = f.x * QKSCALE;
                q[i*8 + p*2 + 1] = f.y * QKSCALE;
            }
        }
    }
    __syncthreads();
    float s[NTOK];
    #pragma unroll
    for (int j = 0; j < NTOK; j++) {
        const float4* kr = (const float4*)&k_s[j * HD];
        float a = 0.f;
        #pragma unroll
        for (int d4 = 0; d4 < 8; d4++) {
            float4 kv = kr[d4];
            a = fmaf(q[d4*4+0], kv.x, a);
            a = fmaf(q[d4*4+1], kv.y, a);
            a = fmaf(q[d4*4+2], kv.z, a);
            a = fmaf(q[d4*4+3], kv.w, a);
        }
        s[j] = a;
    }
    if (shifted) {
        #pragma unroll
        for (int j = 0; j < NTOK; j++)
            if (lab_s[j] != mylab) s[j] = -1e30f;
    }
    float m = -1e30f;
    #pragma unroll
    for (int j = 0; j < NTOK; j++) m = fmaxf(m, s[j]);
    float sum = 0.f;
    #pragma unroll
    for (int j = 0; j < NTOK; j++) { s[j] = __expf(s[j] - m); sum += s[j]; }
    float inv = 1.f / sum;
    float o[HD];
    #pragma unroll
    for (int d = 0; d < HD; d++) o[d] = 0.f;
    #pragma unroll
    for (int j = 0; j < NTOK; j++) {
        float p = s[j];
        const float4* vr = (const float4*)&v_s[j * HD];
        #pragma unroll
        for (int d4 = 0; d4 < 8; d4++) {
            float4 vv = vr[d4];
            o[d4*4+0] = fmaf(p, vv.x, o[d4*4+0]);
            o[d4*4+1] = fmaf(p, vv.y, o[d4*4+1]);
            o[d4*4+2] = fmaf(p, vv.z, o[d4*4+2]);
            o[d4*4+3] = fmaf(p, vv.w, o[d4*4+3]);
        }
    }
    __half* orow = &out[(size_t)(wi * NTOK + n) * CC + head * HD];
    #pragma unroll
    for (int i = 0; i < 8; i++) {
        float4 t = make_float4(o[i*4]*inv, o[i*4+1]*inv, o[i*4+2]*inv, o[i*4+3]*inv);
        *(uint2*)&orow[i * 4] = f4_to_h4(t);
    }
}

// ---------------- patch-merge gather + LN(512), half out --------------------
__global__ __launch_bounds__(128) void pm_ln_kernel(
    const float* __restrict__ x, const float* __restrict__ gam,
    const float* __restrict__ bet, __half* __restrict__ out)
{
    int lane = threadIdx.x & 31;
    int warp = threadIdx.x >> 5;
    int i = blockIdx.x * 4 + warp;
    int b = i / 2304, pos = i % 2304;
    int oh = pos / 48, ow = pos % 48;
    int base = b * LL;
    int src[4];
    src[0] = base + (2*oh    ) * WW + 2*ow;
    src[1] = base + (2*oh + 1) * WW + 2*ow;
    src[2] = base + (2*oh    ) * WW + 2*ow + 1;
    src[3] = base + (2*oh + 1) * WW + 2*ow + 1;
    float4 v[4];
    float s1 = 0.f, s2 = 0.f;
    #pragma unroll
    for (int k = 0; k < 4; k++) {
        v[k] = *(const float4*)&x[(size_t)src[k] * CC + lane * 4];
        s1 += v[k].x + v[k].y + v[k].z + v[k].w;
        s2 += v[k].x*v[k].x + v[k].y*v[k].y + v[k].z*v[k].z + v[k].w*v[k].w;
    }
    #pragma unroll
    for (int o = 16; o; o >>= 1) {
        s1 += __shfl_xor_sync(0xffffffffu, s1, o);
        s2 += __shfl_xor_sync(0xffffffffu, s2, o);
    }
    float mean = s1 * (1.f / 512.f);
    float var  = s2 * (1.f / 512.f) - mean * mean;
    float rstd = rsqrtf(var + 1e-5f);
    #pragma unroll
    for (int k = 0; k < 4; k++) {
        int col = k * CC + lane * 4;
        float4 g4 = *(const float4*)&gam[col];
        float4 b4 = *(const float4*)&bet[col];
        float4 o4;
        o4.x = (v[k].x - mean) * rstd * g4.x + b4.x;
        o4.y = (v[k].y - mean) * rstd * g4.y + b4.y;
        o4.z = (v[k].z - mean) * rstd * g4.z + b4.z;
        o4.w = (v[k].w - mean) * rstd * g4.w + b4.w;
        *(uint2*)&out[(size_t)i * 512 + col] = f4_to_h4(o4);
    }
}

// ---------------- host orchestration ----------------------------------------
static void run_block(const float* xin, float* xout, const float* const* p, int shift,
                      const __half* qkv_t, const __half* proj_t,
                      const __half* fc1_t, const __half* fc2_t,
                      __half* xw, __half* qkv, __half* att, __half* h)
{
    ln_kernel<true><<<ROWS/4, 128>>>(xin, p[0], p[1], xw, shift);
    gemm_mma<0,__half><<<dim3(ROWS/128, 3), 256, GM_SMEM>>>(xw, qkv_t, p[3], qkv, nullptr, ROWS, 384, CC, 0);
    attn_kernel<<<(ROWS/NTOK)*HEADS, 64>>>(qkv, att, shift > 0 ? 1 : 0);
    gemm_mma<1,float><<<dim3(ROWS/128, 1), 256, GM_SMEM>>>(att, proj_t, p[5], xout, xin, ROWS, CC, CC, shift);
    ln_kernel<false><<<ROWS/4, 128>>>(xout, p[6], p[7], xw, 0);
    gemm_mma<2,__half><<<dim3(ROWS/128, 4), 256, GM_SMEM>>>(xw, fc1_t, p[9], h, nullptr, ROWS, 512, CC, 0);
    gemm_mma<3,float><<<dim3(ROWS/128, 1), 256, GM_SMEM>>>(h, fc2_t, p[11], xout, xout, ROWS, CC, 512, 0);
}

extern "C" void kernel_launch(void* const* d_in, const int* in_sizes, int n_in,
                              void* d_out, int out_size)
{
    (void)in_sizes; (void)n_in; (void)out_size;
    const float* x = (const float*)d_in[0];
    const float* pa[12];
    const float* pb[12];
    for (int i = 0; i < 12; i++) pa[i] = (const float*)d_in[1 + i];
    for (int i = 0; i < 12; i++) pb[i] = (const float*)d_in[13 + i];
    const float* mln_g = (const float*)d_in[25];
    const float* mln_b = (const float*)d_in[26];
    const float* red_w = (const float*)d_in[27];
    float* out = (float*)d_out;

    __half *xw, *qkv, *att, *h, *wt;
    float *xa, *xb;
    cudaGetSymbolAddress((void**)&xw,  g_xw);
    cudaGetSymbolAddress((void**)&qkv, g_qkv);
    cudaGetSymbolAddress((void**)&att, g_att);
    cudaGetSymbolAddress((void**)&xa,  g_xa);
    cudaGetSymbolAddress((void**)&xb,  g_xb);
    cudaGetSymbolAddress((void**)&h,   g_h);
    cudaGetSymbolAddress((void**)&wt,  g_wt);

    static bool attr_done = false;
    if (!attr_done) {
        cudaFuncSetAttribute(gemm_mma<0,__half>, cudaFuncAttributeMaxDynamicSharedMemorySize, GM_SMEM);
        cudaFuncSetAttribute(gemm_mma<1,float>,  cudaFuncAttributeMaxDynamicSharedMemorySize, GM_SMEM);
        cudaFuncSetAttribute(gemm_mma<2,__half>, cudaFuncAttributeMaxDynamicSharedMemorySize, GM_SMEM);
        cudaFuncSetAttribute(gemm_mma<3,float>,  cudaFuncAttributeMaxDynamicSharedMemorySize, GM_SMEM);
        cudaFuncSetAttribute(gemm_mma<4,float>,  cudaFuncAttributeMaxDynamicSharedMemorySize, GM_SMEM);
        attr_done = true;
    }

    __half* a_qkv_t  = wt;            // 384*128
    __half* a_proj_t = wt + 49152;    // 128*128
    __half* a_fc1_t  = wt + 65536;    // 512*128
    __half* a_fc2_t  = wt + 131072;   // 128*512
    __half* b_qkv_t  = wt + 196608;
    __half* b_proj_t = wt + 245760;
    __half* b_fc1_t  = wt + 262144;
    __half* b_fc2_t  = wt + 327680;
    __half* red_t    = wt + 393216;   // 256*512

    TPJobs jb;
    jb.src[0] = pa[2];  jb.dst[0] = a_qkv_t;  jb.K[0] = 128; jb.N[0] = 384;
    jb.src[1] = pa[4];  jb.dst[1] = a_proj_t; jb.K[1] = 128; jb.N[1] = 128;
    jb.src[2] = pa[8];  jb.dst[2] = a_fc1_t;  jb.K[2] = 128; jb.N[2] = 512;
    jb.src[3] = pa[10]; jb.dst[3] = a_fc2_t;  jb.K[3] = 512; jb.N[3] = 128;
    jb.src[4] = pb[2];  jb.dst[4] = b_qkv_t;  jb.K[4] = 128; jb.N[4] = 384;
    jb.src[5] = pb[4];  jb.dst[5] = b_proj_t; jb.K[5] = 128; jb.N[5] = 128;
    jb.src[6] = pb[8];  jb.dst[6] = b_fc1_t;  jb.K[6] = 128; jb.N[6] = 512;
    jb.src[7] = pb[10]; jb.dst[7] = b_fc2_t;  jb.K[7] = 512; jb.N[7] = 128;
    jb.src[8] = red_w;  jb.dst[8] = red_t;    jb.K[8] = 512; jb.N[8] = 256;
    transpose_all<<<dim3(16, 16, 9), 256>>>(jb);

    run_block(x,  xa, pa, 0, a_qkv_t, a_proj_t, a_fc1_t, a_fc2_t, xw, qkv, att, h);
    run_block(xa, xb, pb, 4, b_qkv_t, b_proj_t, b_fc1_t, b_fc2_t, xw, qkv, att, h);

    pm_ln_kernel<<<(ROWS/4)/NTOK * 16, 128>>>(xb, mln_g, mln_b, att);
    gemm_mma<4,float><<<dim3((ROWS/4)/128, 2), 256, GM_SMEM>>>(att, red_t, nullptr, out, nullptr,
                                                               ROWS/4, 256, 512, 0);
}

// round 7
// speedup vs baseline: 2.1541x; 2.1541x over previous
#include <cuda_runtime.h>
#include <cuda_fp16.h>
#include <cstdint>

// Problem constants
#define BATCH 8
#define HH 96
#define WW 96
#define CC 128
#define LL (HH*WW)            // 9216
#define ROWS (BATCH*LL)       // 73728
#define NWIN 144
#define WS 8
#define NTOK 64
#define HEADS 4
#define HD 32
#define QKSCALE 0.17677669529663687f

// ---------------- scratch -----------------
__device__ __half g_xw [ (size_t)ROWS*CC ];
__device__ __half g_qkv[ (size_t)ROWS*3*CC ];
__device__ __half g_att[ (size_t)ROWS*CC ];
__device__ float  g_xa [ (size_t)ROWS*CC ];
__device__ float  g_xb [ (size_t)ROWS*CC ];
__device__ __half g_h  [ (size_t)ROWS*4*CC ];
__device__ __half g_wt [ 524288 ];

__device__ __forceinline__ uint32_t smem_u32(const void* p) {
    uint32_t a;
    asm("{ .reg .u64 t; cvta.to.shared.u64 t, %1; cvt.u32.u64 %0, t; }" : "=r"(a) : "l"(p));
    return a;
}
__device__ __forceinline__ float gelu_exact(float x) {
    return 0.5f * x * (1.f + erff(x * 0.70710678118654752f));
}
__device__ __forceinline__ uint2 f4_to_h4(float4 v) {
    union { uint2 u; __half2 h[2]; } cv;
    cv.h[0] = __floats2half2_rn(v.x, v.y);
    cv.h[1] = __floats2half2_rn(v.z, v.w);
    return cv.u;
}
__device__ __forceinline__ uint32_t h2pack(float a, float b) {
    union { uint32_t u; __half2 h; } cv;
    cv.h = __floats2half2_rn(a, b);
    return cv.u;
}

#define LDSM4(r, addr) \
    asm volatile("ldmatrix.sync.aligned.m8n8.x4.shared.b16 {%0,%1,%2,%3},[%4];" \
        : "=r"((r)[0]), "=r"((r)[1]), "=r"((r)[2]), "=r"((r)[3]) : "r"(addr))
#define LDSM4T(r, addr) \
    asm volatile("ldmatrix.sync.aligned.m8n8.x4.trans.shared.b16 {%0,%1,%2,%3},[%4];" \
        : "=r"((r)[0]), "=r"((r)[1]), "=r"((r)[2]), "=r"((r)[3]) : "r"(addr))
#define MMA16816(acc, a, b0, b1) \
    asm volatile("mma.sync.aligned.m16n8k16.row.col.f32.f16.f16.f32 " \
        "{%0,%1,%2,%3},{%4,%5,%6,%7},{%8,%9},{%0,%1,%2,%3};" \
        : "+f"((acc)[0]), "+f"((acc)[1]), "+f"((acc)[2]), "+f"((acc)[3]) \
        : "r"((a)[0]), "r"((a)[1]), "r"((a)[2]), "r"((a)[3]), "r"(b0), "r"(b1))

// ---------------- LayerNorm (+ optional gather), half output ----------------
template<bool GATHER>
__global__ __launch_bounds__(128) void ln_kernel(
    const float* __restrict__ x, const float* __restrict__ gam,
    const float* __restrict__ bet, __half* __restrict__ out, int shift)
{
    int lane = threadIdx.x & 31;
    int warp = threadIdx.x >> 5;
    int r = blockIdx.x * 4 + warp;
    const float* src;
    if (GATHER) {
        int wi = r >> 6, n = r & 63;
        int b  = wi / NWIN, wl = wi % NWIN;
        int whi = wl / 12, wwi = wl % 12;
        int h0 = whi * 8 + (n >> 3), w0 = wwi * 8 + (n & 7);
        int hs = h0 + shift; if (hs >= HH) hs -= HH;
        int ws_ = w0 + shift; if (ws_ >= WW) ws_ -= WW;
        src = &x[(size_t)(b * LL + hs * WW + ws_) * CC];
    } else {
        src = &x[(size_t)r * CC];
    }
    float4 v = *(const float4*)&src[lane * 4];
    float s1 = v.x + v.y + v.z + v.w;
    float s2 = v.x*v.x + v.y*v.y + v.z*v.z + v.w*v.w;
    #pragma unroll
    for (int o = 16; o; o >>= 1) {
        s1 += __shfl_xor_sync(0xffffffffu, s1, o);
        s2 += __shfl_xor_sync(0xffffffffu, s2, o);
    }
    float mean = s1 * (1.f / CC);
    float var  = s2 * (1.f / CC) - mean * mean;
    float rstd = rsqrtf(var + 1e-5f);
    float4 g4 = *(const float4*)&gam[lane * 4];
    float4 b4 = *(const float4*)&bet[lane * 4];
    float4 o4;
    o4.x = (v.x - mean) * rstd * g4.x + b4.x;
    o4.y = (v.y - mean) * rstd * g4.y + b4.y;
    o4.z = (v.z - mean) * rstd * g4.z + b4.z;
    o4.w = (v.w - mean) * rstd * g4.w + b4.w;
    *(uint2*)&out[(size_t)r * CC + lane * 4] = f4_to_h4(o4);
}

// ---------------- batched weight transpose ----------------------------------
struct TPJobs {
    const float* src[9];
    __half* dst[9];
    int K[9];
    int N[9];
};
__global__ __launch_bounds__(256) void transpose_all(TPJobs jb)
{
    __shared__ float t[32][33];
    int m = blockIdx.z;
    int K = jb.K[m], N = jb.N[m];
    int k0 = blockIdx.x * 32, n0 = blockIdx.y * 32;
    if (k0 >= K || n0 >= N) return;
    const float* src = jb.src[m];
    __half* dst = jb.dst[m];
    int x = threadIdx.x & 31, y = threadIdx.x >> 5;
    #pragma unroll
    for (int i = 0; i < 32; i += 8)
        t[y + i][x] = src[(size_t)(k0 + y + i) * N + n0 + x];
    __syncthreads();
    #pragma unroll
    for (int i = 0; i < 32; i += 8)
        dst[(size_t)(n0 + y + i) * K + k0 + x] = __float2half_rn(t[x][y + i]);
}

// ---------------- fp16 mma.sync GEMM (m16n8k16), 2-stage (R4-proven) ---------
#define AS_STRIDE 40
#define TILE_H   (128*AS_STRIDE)
#define GM_SMEM  (4*TILE_H*2)              // 40960 bytes

__device__ __forceinline__ void copy_chunk(
    const __half* __restrict__ A, const __half* __restrict__ B,
    int bm, int bn, int K, int k0, __half* sA, __half* sB, int tid)
{
    uint32_t a_s = smem_u32(sA), b_s = smem_u32(sB);
    #pragma unroll
    for (int i = 0; i < 2; i++) {
        int idx = tid + i * 256;
        int row = idx >> 2, q = idx & 3;
        const __half* ga = &A[(size_t)(bm + row) * K + k0 + q * 8];
        const __half* gb = &B[(size_t)(bn + row) * K + k0 + q * 8];
        uint32_t so = (row * AS_STRIDE + q * 8) * 2;
        asm volatile("cp.async.cg.shared.global [%0],[%1],16;" :: "r"(a_s + so), "l"(ga));
        asm volatile("cp.async.cg.shared.global [%0],[%1],16;" :: "r"(b_s + so), "l"(gb));
    }
    asm volatile("cp.async.commit_group;" ::: "memory");
}

template<int EPI, typename OT>
__global__ __launch_bounds__(256)
void gemm_mma(const __half* __restrict__ A, const __half* __restrict__ B,
              const float* __restrict__ bias, OT* __restrict__ C,
              const float* __restrict__ res, int M, int N, int K, int shift)
{
    extern __shared__ __half smh[];
    __half* bufA[2] = { smh,          smh + 2*TILE_H };
    __half* bufB[2] = { smh + TILE_H, smh + 3*TILE_H };
    int tid = threadIdx.x, lane = tid & 31, wid = tid >> 5;
    int g = lane >> 2, kq = lane & 3;
    int warpM = wid & 3, warpN = wid >> 2;
    int bm = blockIdx.x * 128, bn = blockIdx.y * 128;

    float acc[2][8][4];
    #pragma unroll
    for (int i = 0; i < 2; i++)
        #pragma unroll
        for (int j = 0; j < 8; j++)
            #pragma unroll
            for (int q = 0; q < 4; q++) acc[i][j][q] = 0.f;

    int nc = K >> 5;
    copy_chunk(A, B, bm, bn, K, 0, bufA[0], bufB[0], tid);

    uint32_t a_off = (((warpM * 32 + (lane & 15)) * AS_STRIDE) + ((lane >> 4) << 3)) * 2;
    uint32_t b_off = (((warpN * 64 + (lane & 7) + (((lane >> 4) & 1) << 3)) * AS_STRIDE)
                     + (((lane >> 3) & 1) << 3)) * 2;

    for (int c = 0; c < nc; c++) {
        if (c + 1 < nc) {
            copy_chunk(A, B, bm, bn, K, (c + 1) << 5, bufA[(c+1)&1], bufB[(c+1)&1], tid);
            asm volatile("cp.async.wait_group 1;" ::: "memory");
        } else {
            asm volatile("cp.async.wait_group 0;" ::: "memory");
        }
        __syncthreads();

        uint32_t ab = smem_u32(bufA[c&1]) + a_off;
        uint32_t bb = smem_u32(bufB[c&1]) + b_off;
        #pragma unroll
        for (int ks = 0; ks < 2; ks++) {
            uint32_t a[2][4], b[4][4];
            LDSM4(a[0], ab + ks * 32);
            LDSM4(a[1], ab + 16 * AS_STRIDE * 2 + ks * 32);
            #pragma unroll
            for (int j16 = 0; j16 < 4; j16++)
                LDSM4(b[j16], bb + j16 * 16 * AS_STRIDE * 2 + ks * 32);
            #pragma unroll
            for (int i = 0; i < 2; i++)
                #pragma unroll
                for (int j = 0; j < 8; j++) {
                    uint32_t b0 = b[j >> 1][(j & 1) * 2];
                    uint32_t b1 = b[j >> 1][(j & 1) * 2 + 1];
                    MMA16816(acc[i][j], a[i], b0, b1);
                }
        }
        __syncthreads();
    }

    #pragma unroll
    for (int i = 0; i < 2; i++) {
        #pragma unroll
        for (int rr = 0; rr < 2; rr++) {
            int gr = bm + warpM * 32 + i * 16 + g + rr * 8;
            int dst = gr;
            if (EPI == 1) {
                int wi = gr >> 6, n = gr & 63;
                int b  = wi / NWIN, wl = wi % NWIN;
                int whi = wl / 12, wwi = wl % 12;
                int h0 = whi * 8 + (n >> 3), w0 = wwi * 8 + (n & 7);
                int h = h0 + shift; if (h >= HH) h -= HH;
                int w = w0 + shift; if (w >= WW) w -= WW;
                dst = b * LL + h * WW + w;
            }
            #pragma unroll
            for (int j = 0; j < 8; j++) {
                int col = bn + warpN * 64 + j * 8 + 2 * kq;
                float vx = acc[i][j][rr*2+0];
                float vy = acc[i][j][rr*2+1];
                if (EPI != 4) {
                    vx += __ldg(&bias[col]);
                    vy += __ldg(&bias[col+1]);
                }
                if (EPI == 2) { vx = gelu_exact(vx); vy = gelu_exact(vy); }
                if (EPI == 1 || EPI == 3) {
                    float2 r2 = *(const float2*)&res[(size_t)dst * N + col];
                    vx += r2.x; vy += r2.y;
                }
                if (sizeof(OT) == 2) {
                    *(__half2*)&((__half*)C)[(size_t)dst * N + col] = __floats2half2_rn(vx, vy);
                } else {
                    *(float2*)&((float*)C)[(size_t)dst * N + col] = make_float2(vx, vy);
                }
            }
        }
    }
}

// ---------------- MMA windowed attention -------------------------------------
// One CTA per window (64 tokens), 4 warps = 4 heads. qkv tile staged in smem.
#define AT_STRIDE 400                       // halves per row (384 + 16 pad)
#define AT_SMEM   (64*AT_STRIDE*2 + 64*4)   // 51456 bytes

template<bool SHIFTED>
__global__ __launch_bounds__(128) void attn_mma(
    const __half* __restrict__ qkv, __half* __restrict__ out)
{
    extern __shared__ __half smw[];
    int* lab = (int*)(smw + 64*AT_STRIDE);
    int tid = threadIdx.x, lane = tid & 31, h = tid >> 5;
    int wi = blockIdx.x;

    // stage the 64x384 qkv tile
    const uint4* gsrc = (const uint4*)(qkv + (size_t)wi * 64 * 384);
    #pragma unroll
    for (int i = 0; i < 24; i++) {
        int idx = tid + i * 128;            // 0..3071
        int row = idx / 48, seg = idx % 48;
        *(uint4*)&smw[row * AT_STRIDE + seg * 8] = gsrc[row * 48 + seg];
    }
    if (SHIFTED && tid < 64) {
        int wl = wi % NWIN;
        int whi = wl / 12, wwi = wl % 12;
        int hh = whi * 8 + (tid >> 3), ww_ = wwi * 8 + (tid & 7);
        int hr = (hh < HH - WS) ? 0 : ((hh < HH - 4) ? 1 : 2);
        int wr = (ww_ < WW - WS) ? 0 : ((ww_ < WW - 4) ? 1 : 2);
        lab[tid] = hr * 3 + wr;
    }
    __syncthreads();

    uint32_t sbase = smem_u32(smw);
    int qbase = h * 32;
    int kbase = 128 + h * 32;
    int vbase = 256 + h * 32;

    // ldmatrix lane addressing components
    uint32_t q_row  = lane & 15;
    uint32_t q_colh = (lane >> 4) << 3;
    uint32_t k_row  = (lane & 7) + (((lane >> 4) & 1) << 3);
    uint32_t k_colh = ((lane >> 3) & 1) << 3;
    uint32_t v_row  = lane & 15;
    uint32_t v_colh = (lane >> 4) << 3;

    #pragma unroll
    for (int mt = 0; mt < 4; mt++) {
        // S = Q @ K^T for 16 rows
        float sAcc[8][4];
        #pragma unroll
        for (int j = 0; j < 8; j++)
            #pragma unroll
            for (int q = 0; q < 4; q++) sAcc[j][q] = 0.f;
        #pragma unroll
        for (int kt = 0; kt < 2; kt++) {
            uint32_t a[4];
            LDSM4(a, sbase + ((mt*16 + q_row) * AT_STRIDE + qbase + q_colh + kt*16) * 2);
            #pragma unroll
            for (int j16 = 0; j16 < 4; j16++) {
                uint32_t b[4];
                LDSM4(b, sbase + ((j16*16 + k_row) * AT_STRIDE + kbase + k_colh + kt*16) * 2);
                MMA16816(sAcc[2*j16],   a, b[0], b[1]);
                MMA16816(sAcc[2*j16+1], a, b[2], b[3]);
            }
        }

        int row_lo = mt*16 + (lane >> 2);
        int row_hi = row_lo + 8;
        if (SHIFTED) {
            int ll = lab[row_lo], lh = lab[row_hi];
            #pragma unroll
            for (int j = 0; j < 8; j++) {
                int c0 = j*8 + 2*(lane & 3);
                int lc0 = lab[c0], lc1 = lab[c0+1];
                if (lc0 != ll) sAcc[j][0] = -1e30f;
                if (lc1 != ll) sAcc[j][1] = -1e30f;
                if (lc0 != lh) sAcc[j][2] = -1e30f;
                if (lc1 != lh) sAcc[j][3] = -1e30f;
            }
        }
        // row max
        float mlo = -1e30f, mhi = -1e30f;
        #pragma unroll
        for (int j = 0; j < 8; j++) {
            mlo = fmaxf(mlo, fmaxf(sAcc[j][0], sAcc[j][1]));
            mhi = fmaxf(mhi, fmaxf(sAcc[j][2], sAcc[j][3]));
        }
        mlo = fmaxf(mlo, __shfl_xor_sync(0xffffffffu, mlo, 1));
        mlo = fmaxf(mlo, __shfl_xor_sync(0xffffffffu, mlo, 2));
        mhi = fmaxf(mhi, __shfl_xor_sync(0xffffffffu, mhi, 1));
        mhi = fmaxf(mhi, __shfl_xor_sync(0xffffffffu, mhi, 2));
        // exp + sums + fp16 P frags
        float slo = 0.f, shi = 0.f;
        uint32_t pf[8][2];
        #pragma unroll
        for (int j = 0; j < 8; j++) {
            float e0 = __expf((sAcc[j][0] - mlo) * QKSCALE);
            float e1 = __expf((sAcc[j][1] - mlo) * QKSCALE);
            float e2 = __expf((sAcc[j][2] - mhi) * QKSCALE);
            float e3 = __expf((sAcc[j][3] - mhi) * QKSCALE);
            slo += e0 + e1; shi += e2 + e3;
            pf[j][0] = h2pack(e0, e1);
            pf[j][1] = h2pack(e2, e3);
        }
        slo += __shfl_xor_sync(0xffffffffu, slo, 1);
        slo += __shfl_xor_sync(0xffffffffu, slo, 2);
        shi += __shfl_xor_sync(0xffffffffu, shi, 1);
        shi += __shfl_xor_sync(0xffffffffu, shi, 2);
        float ilo = 1.f / slo, ihi = 1.f / shi;

        // O = P @ V  (k = tokens, 4 k16 steps; n = 32, 4 n8 tiles)
        float oAcc[4][4];
        #pragma unroll
        for (int j = 0; j < 4; j++)
            #pragma unroll
            for (int q = 0; q < 4; q++) oAcc[j][q] = 0.f;
        #pragma unroll
        for (int t = 0; t < 4; t++) {
            uint32_t a[4] = { pf[2*t][0], pf[2*t][1], pf[2*t+1][0], pf[2*t+1][1] };
            #pragma unroll
            for (int n16 = 0; n16 < 2; n16++) {
                uint32_t b[4];
                LDSM4T(b, sbase + ((t*16 + v_row) * AT_STRIDE + vbase + n16*16 + v_colh) * 2);
                MMA16816(oAcc[2*n16],   a, b[0], b[1]);
                MMA16816(oAcc[2*n16+1], a, b[2], b[3]);
            }
        }

        // store 16 rows of O
        __half* orow_lo = &out[(size_t)(wi*64 + row_lo) * CC + h*32];
        __half* orow_hi = &out[(size_t)(wi*64 + row_hi) * CC + h*32];
        #pragma unroll
        for (int j = 0; j < 4; j++) {
            int col = j*8 + 2*(lane & 3);
            *(__half2*)&orow_lo[col] = __floats2half2_rn(oAcc[j][0]*ilo, oAcc[j][1]*ilo);
            *(__half2*)&orow_hi[col] = __floats2half2_rn(oAcc[j][2]*ihi, oAcc[j][3]*ihi);
        }
    }
}

// ---------------- patch-merge gather + LN(512), half out --------------------
__global__ __launch_bounds__(128) void pm_ln_kernel(
    const float* __restrict__ x, const float* __restrict__ gam,
    const float* __restrict__ bet, __half* __restrict__ out)
{
    int lane = threadIdx.x & 31;
    int warp = threadIdx.x >> 5;
    int i = blockIdx.x * 4 + warp;
    int b = i / 2304, pos = i % 2304;
    int oh = pos / 48, ow = pos % 48;
    int base = b * LL;
    int src[4];
    src[0] = base + (2*oh    ) * WW + 2*ow;
    src[1] = base + (2*oh + 1) * WW + 2*ow;
    src[2] = base + (2*oh    ) * WW + 2*ow + 1;
    src[3] = base + (2*oh + 1) * WW + 2*ow + 1;
    float4 v[4];
    float s1 = 0.f, s2 = 0.f;
    #pragma unroll
    for (int k = 0; k < 4; k++) {
        v[k] = *(const float4*)&x[(size_t)src[k] * CC + lane * 4];
        s1 += v[k].x + v[k].y + v[k].z + v[k].w;
        s2 += v[k].x*v[k].x + v[k].y*v[k].y + v[k].z*v[k].z + v[k].w*v[k].w;
    }
    #pragma unroll
    for (int o = 16; o; o >>= 1) {
        s1 += __shfl_xor_sync(0xffffffffu, s1, o);
        s2 += __shfl_xor_sync(0xffffffffu, s2, o);
    }
    float mean = s1 * (1.f / 512.f);
    float var  = s2 * (1.f / 512.f) - mean * mean;
    float rstd = rsqrtf(var + 1e-5f);
    #pragma unroll
    for (int k = 0; k < 4; k++) {
        int col = k * CC + lane * 4;
        float4 g4 = *(const float4*)&gam[col];
        float4 b4 = *(const float4*)&bet[col];
        float4 o4;
        o4.x = (v[k].x - mean) * rstd * g4.x + b4.x;
        o4.y = (v[k].y - mean) * rstd * g4.y + b4.y;
        o4.z = (v[k].z - mean) * rstd * g4.z + b4.z;
        o4.w = (v[k].w - mean) * rstd * g4.w + b4.w;
        *(uint2*)&out[(size_t)i * 512 + col] = f4_to_h4(o4);
    }
}

// ---------------- host orchestration ----------------------------------------
static void run_block(const float* xin, float* xout, const float* const* p, int shift,
                      const __half* qkv_t, const __half* proj_t,
                      const __half* fc1_t, const __half* fc2_t,
                      __half* xw, __half* qkv, __half* att, __half* h)
{
    ln_kernel<true><<<ROWS/4, 128>>>(xin, p[0], p[1], xw, shift);
    gemm_mma<0,__half><<<dim3(ROWS/128, 3), 256, GM_SMEM>>>(xw, qkv_t, p[3], qkv, nullptr, ROWS, 384, CC, 0);
    if (shift > 0)
        attn_mma<true><<<ROWS/NTOK, 128, AT_SMEM>>>(qkv, att);
    else
        attn_mma<false><<<ROWS/NTOK, 128, AT_SMEM>>>(qkv, att);
    gemm_mma<1,float><<<dim3(ROWS/128, 1), 256, GM_SMEM>>>(att, proj_t, p[5], xout, xin, ROWS, CC, CC, shift);
    ln_kernel<false><<<ROWS/4, 128>>>(xout, p[6], p[7], xw, 0);
    gemm_mma<2,__half><<<dim3(ROWS/128, 4), 256, GM_SMEM>>>(xw, fc1_t, p[9], h, nullptr, ROWS, 512, CC, 0);
    gemm_mma<3,float><<<dim3(ROWS/128, 1), 256, GM_SMEM>>>(h, fc2_t, p[11], xout, xout, ROWS, CC, 512, 0);
}

extern "C" void kernel_launch(void* const* d_in, const int* in_sizes, int n_in,
                              void* d_out, int out_size)
{
    (void)in_sizes; (void)n_in; (void)out_size;
    const float* x = (const float*)d_in[0];
    const float* pa[12];
    const float* pb[12];
    for (int i = 0; i < 12; i++) pa[i] = (const float*)d_in[1 + i];
    for (int i = 0; i < 12; i++) pb[i] = (const float*)d_in[13 + i];
    const float* mln_g = (const float*)d_in[25];
    const float* mln_b = (const float*)d_in[26];
    const float* red_w = (const float*)d_in[27];
    float* out = (float*)d_out;

    __half *xw, *qkv, *att, *h, *wt;
    float *xa, *xb;
    cudaGetSymbolAddress((void**)&xw,  g_xw);
    cudaGetSymbolAddress((void**)&qkv, g_qkv);
    cudaGetSymbolAddress((void**)&att, g_att);
    cudaGetSymbolAddress((void**)&xa,  g_xa);
    cudaGetSymbolAddress((void**)&xb,  g_xb);
    cudaGetSymbolAddress((void**)&h,   g_h);
    cudaGetSymbolAddress((void**)&wt,  g_wt);

    static bool attr_done = false;
    if (!attr_done) {
        cudaFuncSetAttribute(attn_mma<false>, cudaFuncAttributeMaxDynamicSharedMemorySize, AT_SMEM);
        cudaFuncSetAttribute(attn_mma<true>,  cudaFuncAttributeMaxDynamicSharedMemorySize, AT_SMEM);
        attr_done = true;
    }

    __half* a_qkv_t  = wt;            // 384*128
    __half* a_proj_t = wt + 49152;    // 128*128
    __half* a_fc1_t  = wt + 65536;    // 512*128
    __half* a_fc2_t  = wt + 131072;   // 128*512
    __half* b_qkv_t  = wt + 196608;
    __half* b_proj_t = wt + 245760;
    __half* b_fc1_t  = wt + 262144;
    __half* b_fc2_t  = wt + 327680;
    __half* red_t    = wt + 393216;   // 256*512

    TPJobs jb;
    jb.src[0] = pa[2];  jb.dst[0] = a_qkv_t;  jb.K[0] = 128; jb.N[0] = 384;
    jb.src[1] = pa[4];  jb.dst[1] = a_proj_t; jb.K[1] = 128; jb.N[1] = 128;
    jb.src[2] = pa[8];  jb.dst[2] = a_fc1_t;  jb.K[2] = 128; jb.N[2] = 512;
    jb.src[3] = pa[10]; jb.dst[3] = a_fc2_t;  jb.K[3] = 512; jb.N[3] = 128;
    jb.src[4] = pb[2];  jb.dst[4] = b_qkv_t;  jb.K[4] = 128; jb.N[4] = 384;
    jb.src[5] = pb[4];  jb.dst[5] = b_proj_t; jb.K[5] = 128; jb.N[5] = 128;
    jb.src[6] = pb[8];  jb.dst[6] = b_fc1_t;  jb.K[6] = 128; jb.N[6] = 512;
    jb.src[7] = pb[10]; jb.dst[7] = b_fc2_t;  jb.K[7] = 512; jb.N[7] = 128;
    jb.src[8] = red_w;  jb.dst[8] = red_t;    jb.K[8] = 512; jb.N[8] = 256;
    transpose_all<<<dim3(16, 16, 9), 256>>>(jb);

    run_block(x,  xa, pa, 0, a_qkv_t, a_proj_t, a_fc1_t, a_fc2_t, xw, qkv, att, h);
    run_block(xa, xb, pb, 4, b_qkv_t, b_proj_t, b_fc1_t, b_fc2_t, xw, qkv, att, h);

    pm_ln_kernel<<<(ROWS/4)/NTOK * 16, 128>>>(xb, mln_g, mln_b, att);
    gemm_mma<4,float><<<dim3((ROWS/4)/128, 2), 256, GM_SMEM>>>(att, red_t, nullptr, out, nullptr,
                                                               ROWS/4, 256, 512, 0);
}

// round 8
// speedup vs baseline: 2.1878x; 1.0156x over previous
#include <cuda_runtime.h>
#include <cuda_fp16.h>
#include <cstdint>

// Problem constants
#define BATCH 8
#define HH 96
#define WW 96
#define CC 128
#define LL (HH*WW)            // 9216
#define ROWS (BATCH*LL)       // 73728
#define NWIN 144
#define WS 8
#define NTOK 64
#define HEADS 4
#define HD 32
#define QKSCALE 0.17677669529663687f

// ---------------- scratch -----------------
__device__ __half g_xw [ (size_t)ROWS*CC ];
__device__ __half g_qkv[ (size_t)ROWS*3*CC ];
__device__ __half g_att[ (size_t)ROWS*CC ];
__device__ float  g_xa [ (size_t)ROWS*CC ];
__device__ float  g_xb [ (size_t)ROWS*CC ];
__device__ __half g_h  [ (size_t)ROWS*4*CC ];
__device__ __half g_wt [ 524288 ];

__device__ __forceinline__ uint32_t smem_u32(const void* p) {
    uint32_t a;
    asm("{ .reg .u64 t; cvta.to.shared.u64 t, %1; cvt.u32.u64 %0, t; }" : "=r"(a) : "l"(p));
    return a;
}
__device__ __forceinline__ float gelu_exact(float x) {
    return 0.5f * x * (1.f + erff(x * 0.70710678118654752f));
}
__device__ __forceinline__ uint2 f4_to_h4(float4 v) {
    union { uint2 u; __half2 h[2]; } cv;
    cv.h[0] = __floats2half2_rn(v.x, v.y);
    cv.h[1] = __floats2half2_rn(v.z, v.w);
    return cv.u;
}
__device__ __forceinline__ uint32_t h2pack(float a, float b) {
    union { uint32_t u; __half2 h; } cv;
    cv.h = __floats2half2_rn(a, b);
    return cv.u;
}

#define LDSM4(r, addr) \
    asm volatile("ldmatrix.sync.aligned.m8n8.x4.shared.b16 {%0,%1,%2,%3},[%4];" \
        : "=r"((r)[0]), "=r"((r)[1]), "=r"((r)[2]), "=r"((r)[3]) : "r"(addr))
#define LDSM4T(r, addr) \
    asm volatile("ldmatrix.sync.aligned.m8n8.x4.trans.shared.b16 {%0,%1,%2,%3},[%4];" \
        : "=r"((r)[0]), "=r"((r)[1]), "=r"((r)[2]), "=r"((r)[3]) : "r"(addr))
#define MMA16816(acc, a, b0, b1) \
    asm volatile("mma.sync.aligned.m16n8k16.row.col.f32.f16.f16.f32 " \
        "{%0,%1,%2,%3},{%4,%5,%6,%7},{%8,%9},{%0,%1,%2,%3};" \
        : "+f"((acc)[0]), "+f"((acc)[1]), "+f"((acc)[2]), "+f"((acc)[3]) \
        : "r"((a)[0]), "r"((a)[1]), "r"((a)[2]), "r"((a)[3]), "r"(b0), "r"(b1))

// ---------------- LayerNorm gather (only for block-a entry) ------------------
template<bool GATHER>
__global__ __launch_bounds__(128) void ln_kernel(
    const float* __restrict__ x, const float* __restrict__ gam,
    const float* __restrict__ bet, __half* __restrict__ out, int shift)
{
    int lane = threadIdx.x & 31;
    int warp = threadIdx.x >> 5;
    int r = blockIdx.x * 4 + warp;
    const float* src;
    if (GATHER) {
        int wi = r >> 6, n = r & 63;
        int b  = wi / NWIN, wl = wi % NWIN;
        int whi = wl / 12, wwi = wl % 12;
        int h0 = whi * 8 + (n >> 3), w0 = wwi * 8 + (n & 7);
        int hs = h0 + shift; if (hs >= HH) hs -= HH;
        int ws_ = w0 + shift; if (ws_ >= WW) ws_ -= WW;
        src = &x[(size_t)(b * LL + hs * WW + ws_) * CC];
    } else {
        src = &x[(size_t)r * CC];
    }
    float4 v = *(const float4*)&src[lane * 4];
    float s1 = v.x + v.y + v.z + v.w;
    float s2 = v.x*v.x + v.y*v.y + v.z*v.z + v.w*v.w;
    #pragma unroll
    for (int o = 16; o; o >>= 1) {
        s1 += __shfl_xor_sync(0xffffffffu, s1, o);
        s2 += __shfl_xor_sync(0xffffffffu, s2, o);
    }
    float mean = s1 * (1.f / CC);
    float var  = s2 * (1.f / CC) - mean * mean;
    float rstd = rsqrtf(var + 1e-5f);
    float4 g4 = *(const float4*)&gam[lane * 4];
    float4 b4 = *(const float4*)&bet[lane * 4];
    float4 o4;
    o4.x = (v.x - mean) * rstd * g4.x + b4.x;
    o4.y = (v.y - mean) * rstd * g4.y + b4.y;
    o4.z = (v.z - mean) * rstd * g4.z + b4.z;
    o4.w = (v.w - mean) * rstd * g4.w + b4.w;
    *(uint2*)&out[(size_t)r * CC + lane * 4] = f4_to_h4(o4);
}

// ---------------- batched weight transpose ----------------------------------
struct TPJobs {
    const float* src[9];
    __half* dst[9];
    int K[9];
    int N[9];
};
__global__ __launch_bounds__(256) void transpose_all(TPJobs jb)
{
    __shared__ float t[32][33];
    int m = blockIdx.z;
    int K = jb.K[m], N = jb.N[m];
    int k0 = blockIdx.x * 32, n0 = blockIdx.y * 32;
    if (k0 >= K || n0 >= N) return;
    const float* src = jb.src[m];
    __half* dst = jb.dst[m];
    int x = threadIdx.x & 31, y = threadIdx.x >> 5;
    #pragma unroll
    for (int i = 0; i < 32; i += 8)
        t[y + i][x] = src[(size_t)(k0 + y + i) * N + n0 + x];
    __syncthreads();
    #pragma unroll
    for (int i = 0; i < 32; i += 8)
        dst[(size_t)(n0 + y + i) * K + k0 + x] = __float2half_rn(t[x][y + i]);
}

// ---------------- shared GEMM plumbing ---------------------------------------
#define AS_STRIDE 40
#define TILE_H   (128*AS_STRIDE)
#define GM_SMEM  (4*TILE_H*2)              // 40960 bytes

__device__ __forceinline__ void copy_chunk(
    const __half* __restrict__ A, const __half* __restrict__ B,
    int bm, int bn, int K, int k0, __half* sA, __half* sB, int tid)
{
    uint32_t a_s = smem_u32(sA), b_s = smem_u32(sB);
    #pragma unroll
    for (int i = 0; i < 2; i++) {
        int idx = tid + i * 256;
        int row = idx >> 2, q = idx & 3;
        const __half* ga = &A[(size_t)(bm + row) * K + k0 + q * 8];
        const __half* gb = &B[(size_t)(bn + row) * K + k0 + q * 8];
        uint32_t so = (row * AS_STRIDE + q * 8) * 2;
        asm volatile("cp.async.cg.shared.global [%0],[%1],16;" :: "r"(a_s + so), "l"(ga));
        asm volatile("cp.async.cg.shared.global [%0],[%1],16;" :: "r"(b_s + so), "l"(gb));
    }
    asm volatile("cp.async.commit_group;" ::: "memory");
}

// ---------------- general GEMM (EPI 0:+bias | 2:+bias,GELU | 4:plain) --------
template<int EPI, typename OT>
__global__ __launch_bounds__(256)
void gemm_mma(const __half* __restrict__ A, const __half* __restrict__ B,
              const float* __restrict__ bias, OT* __restrict__ C,
              const float* __restrict__ res, int M, int N, int K, int shift)
{
    extern __shared__ __half smh[];
    __half* bufA[2] = { smh,          smh + 2*TILE_H };
    __half* bufB[2] = { smh + TILE_H, smh + 3*TILE_H };
    int tid = threadIdx.x, lane = tid & 31, wid = tid >> 5;
    int g = lane >> 2, kq = lane & 3;
    int warpM = wid & 3, warpN = wid >> 2;
    int bm = blockIdx.x * 128, bn = blockIdx.y * 128;

    float acc[2][8][4];
    #pragma unroll
    for (int i = 0; i < 2; i++)
        #pragma unroll
        for (int j = 0; j < 8; j++)
            #pragma unroll
            for (int q = 0; q < 4; q++) acc[i][j][q] = 0.f;

    int nc = K >> 5;
    copy_chunk(A, B, bm, bn, K, 0, bufA[0], bufB[0], tid);

    uint32_t a_off = (((warpM * 32 + (lane & 15)) * AS_STRIDE) + ((lane >> 4) << 3)) * 2;
    uint32_t b_off = (((warpN * 64 + (lane & 7) + (((lane >> 4) & 1) << 3)) * AS_STRIDE)
                     + (((lane >> 3) & 1) << 3)) * 2;

    for (int c = 0; c < nc; c++) {
        if (c + 1 < nc) {
            copy_chunk(A, B, bm, bn, K, (c + 1) << 5, bufA[(c+1)&1], bufB[(c+1)&1], tid);
            asm volatile("cp.async.wait_group 1;" ::: "memory");
        } else {
            asm volatile("cp.async.wait_group 0;" ::: "memory");
        }
        __syncthreads();

        uint32_t ab = smem_u32(bufA[c&1]) + a_off;
        uint32_t bb = smem_u32(bufB[c&1]) + b_off;
        #pragma unroll
        for (int ks = 0; ks < 2; ks++) {
            uint32_t a[2][4], b[4][4];
            LDSM4(a[0], ab + ks * 32);
            LDSM4(a[1], ab + 16 * AS_STRIDE * 2 + ks * 32);
            #pragma unroll
            for (int j16 = 0; j16 < 4; j16++)
                LDSM4(b[j16], bb + j16 * 16 * AS_STRIDE * 2 + ks * 32);
            #pragma unroll
            for (int i = 0; i < 2; i++)
                #pragma unroll
                for (int j = 0; j < 8; j++) {
                    uint32_t b0 = b[j >> 1][(j & 1) * 2];
                    uint32_t b1 = b[j >> 1][(j & 1) * 2 + 1];
                    MMA16816(acc[i][j], a[i], b0, b1);
                }
        }
        __syncthreads();
    }

    #pragma unroll
    for (int i = 0; i < 2; i++) {
        #pragma unroll
        for (int rr = 0; rr < 2; rr++) {
            int gr = bm + warpM * 32 + i * 16 + g + rr * 8;
            #pragma unroll
            for (int j = 0; j < 8; j++) {
                int col = bn + warpN * 64 + j * 8 + 2 * kq;
                float vx = acc[i][j][rr*2+0];
                float vy = acc[i][j][rr*2+1];
                if (EPI != 4) {
                    vx += __ldg(&bias[col]);
                    vy += __ldg(&bias[col+1]);
                }
                if (EPI == 2) { vx = gelu_exact(vx); vy = gelu_exact(vy); }
                if (sizeof(OT) == 2) {
                    *(__half2*)&((__half*)C)[(size_t)gr * N + col] = __floats2half2_rn(vx, vy);
                } else {
                    *(float2*)&((float*)C)[(size_t)gr * N + col] = make_float2(vx, vy);
                }
            }
        }
    }
}

// ---------------- N=128 GEMM with fused residual + LayerNorm -----------------
// warp tile: 16 rows x 128 cols (8 warps = 128 rows). A row's channels live in
// one lane-quad -> LN via 2 shfl reductions.
// MODE 0: proj  — dst = window-reverse scatter(+shift); C[dst]=res[dst]+y;
//                 LN(y+res) -> lnout[dst] (spatial)
// MODE 1: fc2a  — dst = row; C=res+y; LN -> lnout[gather-inv(row, shift=4)]
// MODE 2: fc2b  — dst = row; C=res+y; no LN
template<int MODE>
__global__ __launch_bounds__(256)
void gemm_ln(const __half* __restrict__ A, const __half* __restrict__ B,
             const float* __restrict__ bias, float* __restrict__ C,
             const float* __restrict__ res, const float* __restrict__ gam,
             const float* __restrict__ bet, __half* __restrict__ lnout,
             int K, int shift)
{
    extern __shared__ __half smh[];
    __half* bufA[2] = { smh,          smh + 2*TILE_H };
    __half* bufB[2] = { smh + TILE_H, smh + 3*TILE_H };
    int tid = threadIdx.x, lane = tid & 31, wid = tid >> 5;
    int g = lane >> 2, kq = lane & 3;
    int bm = blockIdx.x * 128;

    float acc[16][4];
    #pragma unroll
    for (int j = 0; j < 16; j++)
        #pragma unroll
        for (int q = 0; q < 4; q++) acc[j][q] = 0.f;

    int nc = K >> 5;
    copy_chunk(A, B, bm, 0, K, 0, bufA[0], bufB[0], tid);

    uint32_t a_off = (((wid * 16 + (lane & 15)) * AS_STRIDE) + ((lane >> 4) << 3)) * 2;
    uint32_t b_off = ((((lane & 7) + (((lane >> 4) & 1) << 3)) * AS_STRIDE)
                     + (((lane >> 3) & 1) << 3)) * 2;

    for (int c = 0; c < nc; c++) {
        if (c + 1 < nc) {
            copy_chunk(A, B, bm, 0, K, (c + 1) << 5, bufA[(c+1)&1], bufB[(c+1)&1], tid);
            asm volatile("cp.async.wait_group 1;" ::: "memory");
        } else {
            asm volatile("cp.async.wait_group 0;" ::: "memory");
        }
        __syncthreads();

        uint32_t ab = smem_u32(bufA[c&1]) + a_off;
        uint32_t bb = smem_u32(bufB[c&1]) + b_off;
        #pragma unroll
        for (int ks = 0; ks < 2; ks++) {
            uint32_t a[4];
            LDSM4(a, ab + ks * 32);
            #pragma unroll
            for (int j16 = 0; j16 < 8; j16++) {
                uint32_t b[4];
                LDSM4(b, bb + j16 * 16 * AS_STRIDE * 2 + ks * 32);
                MMA16816(acc[2*j16],   a, b[0], b[1]);
                MMA16816(acc[2*j16+1], a, b[2], b[3]);
            }
        }
        __syncthreads();
    }

    // rows handled by this thread
    int r0 = bm + wid * 16 + g;
    int r1 = r0 + 8;
    int dst0, dst1;
    if (MODE == 0) {
        #pragma unroll
        for (int rr = 0; rr < 2; rr++) {
            int gr = rr ? r1 : r0;
            int wi = gr >> 6, n = gr & 63;
            int b  = wi / NWIN, wl = wi % NWIN;
            int whi = wl / 12, wwi = wl % 12;
            int h0 = whi * 8 + (n >> 3), w0 = wwi * 8 + (n & 7);
            int h = h0 + shift; if (h >= HH) h -= HH;
            int w = w0 + shift; if (w >= WW) w -= WW;
            int d = b * LL + h * WW + w;
            if (rr) dst1 = d; else dst0 = d;
        }
    } else {
        dst0 = r0; dst1 = r1;
    }

    // bias + residual, accumulate row stats, write fp32 C
    float vv[16][4];
    float s1a = 0.f, s2a = 0.f, s1b = 0.f, s2b = 0.f;
    #pragma unroll
    for (int j = 0; j < 16; j++) {
        int col = j * 8 + 2 * kq;
        float bx = __ldg(&bias[col]), by = __ldg(&bias[col+1]);
        float2 ra = *(const float2*)&res[(size_t)dst0 * CC + col];
        float2 rb = *(const float2*)&res[(size_t)dst1 * CC + col];
        float v0 = acc[j][0] + bx + ra.x;
        float v1 = acc[j][1] + by + ra.y;
        float v2 = acc[j][2] + bx + rb.x;
        float v3 = acc[j][3] + by + rb.y;
        vv[j][0] = v0; vv[j][1] = v1; vv[j][2] = v2; vv[j][3] = v3;
        *(float2*)&C[(size_t)dst0 * CC + col] = make_float2(v0, v1);
        *(float2*)&C[(size_t)dst1 * CC + col] = make_float2(v2, v3);
        if (MODE != 2) {
            s1a += v0 + v1; s2a += v0*v0 + v1*v1;
            s1b += v2 + v3; s2b += v2*v2 + v3*v3;
        }
    }
    if (MODE == 2) return;

    s1a += __shfl_xor_sync(0xffffffffu, s1a, 1);
    s1a += __shfl_xor_sync(0xffffffffu, s1a, 2);
    s2a += __shfl_xor_sync(0xffffffffu, s2a, 1);
    s2a += __shfl_xor_sync(0xffffffffu, s2a, 2);
    s1b += __shfl_xor_sync(0xffffffffu, s1b, 1);
    s1b += __shfl_xor_sync(0xffffffffu, s1b, 2);
    s2b += __shfl_xor_sync(0xffffffffu, s2b, 1);
    s2b += __shfl_xor_sync(0xffffffffu, s2b, 2);

    float ma = s1a * (1.f/CC), va = s2a * (1.f/CC) - ma*ma;
    float mb = s1b * (1.f/CC), vb = s2b * (1.f/CC) - mb*mb;
    float ra_ = rsqrtf(va + 1e-5f), rb_ = rsqrtf(vb + 1e-5f);

    int ln0, ln1;
    if (MODE == 0) { ln0 = dst0; ln1 = dst1; }
    else {
        #pragma unroll
        for (int rr = 0; rr < 2; rr++) {
            int gr = rr ? r1 : r0;
            int b = gr / LL, rem = gr % LL;
            int h = rem / WW, w = rem % WW;
            int h0 = h - 4; if (h0 < 0) h0 += HH;
            int w0 = w - 4; if (w0 < 0) w0 += WW;
            int r = b * LL + ((h0 >> 3) * 12 + (w0 >> 3)) * 64 + (h0 & 7) * 8 + (w0 & 7);
            if (rr) ln1 = r; else ln0 = r;
        }
    }

    #pragma unroll
    for (int j = 0; j < 16; j++) {
        int col = j * 8 + 2 * kq;
        float gx = __ldg(&gam[col]), gy = __ldg(&gam[col+1]);
        float bx = __ldg(&bet[col]), by = __ldg(&bet[col+1]);
        *(__half2*)&lnout[(size_t)ln0 * CC + col] =
            __floats2half2_rn((vv[j][0]-ma)*ra_*gx+bx, (vv[j][1]-ma)*ra_*gy+by);
        *(__half2*)&lnout[(size_t)ln1 * CC + col] =
            __floats2half2_rn((vv[j][2]-mb)*rb_*gx+bx, (vv[j][3]-mb)*rb_*gy+by);
    }
}

// ---------------- MMA windowed attention (unchanged, proven) -----------------
#define AT_STRIDE 400
#define AT_SMEM   (64*AT_STRIDE*2 + 64*4)

template<bool SHIFTED>
__global__ __launch_bounds__(128) void attn_mma(
    const __half* __restrict__ qkv, __half* __restrict__ out)
{
    extern __shared__ __half smw[];
    int* lab = (int*)(smw + 64*AT_STRIDE);
    int tid = threadIdx.x, lane = tid & 31, h = tid >> 5;
    int wi = blockIdx.x;

    const uint4* gsrc = (const uint4*)(qkv + (size_t)wi * 64 * 384);
    #pragma unroll
    for (int i = 0; i < 24; i++) {
        int idx = tid + i * 128;
        int row = idx / 48, seg = idx % 48;
        *(uint4*)&smw[row * AT_STRIDE + seg * 8] = gsrc[row * 48 + seg];
    }
    if (SHIFTED && tid < 64) {
        int wl = wi % NWIN;
        int whi = wl / 12, wwi = wl % 12;
        int hh = whi * 8 + (tid >> 3), ww_ = wwi * 8 + (tid & 7);
        int hr = (hh < HH - WS) ? 0 : ((hh < HH - 4) ? 1 : 2);
        int wr = (ww_ < WW - WS) ? 0 : ((ww_ < WW - 4) ? 1 : 2);
        lab[tid] = hr * 3 + wr;
    }
    __syncthreads();

    uint32_t sbase = smem_u32(smw);
    int qbase = h * 32;
    int kbase = 128 + h * 32;
    int vbase = 256 + h * 32;

    uint32_t q_row  = lane & 15;
    uint32_t q_colh = (lane >> 4) << 3;
    uint32_t k_row  = (lane & 7) + (((lane >> 4) & 1) << 3);
    uint32_t k_colh = ((lane >> 3) & 1) << 3;
    uint32_t v_row  = lane & 15;
    uint32_t v_colh = (lane >> 4) << 3;

    #pragma unroll
    for (int mt = 0; mt < 4; mt++) {
        float sAcc[8][4];
        #pragma unroll
        for (int j = 0; j < 8; j++)
            #pragma unroll
            for (int q = 0; q < 4; q++) sAcc[j][q] = 0.f;
        #pragma unroll
        for (int kt = 0; kt < 2; kt++) {
            uint32_t a[4];
            LDSM4(a, sbase + ((mt*16 + q_row) * AT_STRIDE + qbase + q_colh + kt*16) * 2);
            #pragma unroll
            for (int j16 = 0; j16 < 4; j16++) {
                uint32_t b[4];
                LDSM4(b, sbase + ((j16*16 + k_row) * AT_STRIDE + kbase + k_colh + kt*16) * 2);
                MMA16816(sAcc[2*j16],   a, b[0], b[1]);
                MMA16816(sAcc[2*j16+1], a, b[2], b[3]);
            }
        }

        int row_lo = mt*16 + (lane >> 2);
        int row_hi = row_lo + 8;
        if (SHIFTED) {
            int ll = lab[row_lo], lh = lab[row_hi];
            #pragma unroll
            for (int j = 0; j < 8; j++) {
                int c0 = j*8 + 2*(lane & 3);
                int lc0 = lab[c0], lc1 = lab[c0+1];
                if (lc0 != ll) sAcc[j][0] = -1e30f;
                if (lc1 != ll) sAcc[j][1] = -1e30f;
                if (lc0 != lh) sAcc[j][2] = -1e30f;
                if (lc1 != lh) sAcc[j][3] = -1e30f;
            }
        }
        float mlo = -1e30f, mhi = -1e30f;
        #pragma unroll
        for (int j = 0; j < 8; j++) {
            mlo = fmaxf(mlo, fmaxf(sAcc[j][0], sAcc[j][1]));
            mhi = fmaxf(mhi, fmaxf(sAcc[j][2], sAcc[j][3]));
        }
        mlo = fmaxf(mlo, __shfl_xor_sync(0xffffffffu, mlo, 1));
        mlo = fmaxf(mlo, __shfl_xor_sync(0xffffffffu, mlo, 2));
        mhi = fmaxf(mhi, __shfl_xor_sync(0xffffffffu, mhi, 1));
        mhi = fmaxf(mhi, __shfl_xor_sync(0xffffffffu, mhi, 2));
        float slo = 0.f, shi = 0.f;
        uint32_t pf[8][2];
        #pragma unroll
        for (int j = 0; j < 8; j++) {
            float e0 = __expf((sAcc[j][0] - mlo) * QKSCALE);
            float e1 = __expf((sAcc[j][1] - mlo) * QKSCALE);
            float e2 = __expf((sAcc[j][2] - mhi) * QKSCALE);
            float e3 = __expf((sAcc[j][3] - mhi) * QKSCALE);
            slo += e0 + e1; shi += e2 + e3;
            pf[j][0] = h2pack(e0, e1);
            pf[j][1] = h2pack(e2, e3);
        }
        slo += __shfl_xor_sync(0xffffffffu, slo, 1);
        slo += __shfl_xor_sync(0xffffffffu, slo, 2);
        shi += __shfl_xor_sync(0xffffffffu, shi, 1);
        shi += __shfl_xor_sync(0xffffffffu, shi, 2);
        float ilo = 1.f / slo, ihi = 1.f / shi;

        float oAcc[4][4];
        #pragma unroll
        for (int j = 0; j < 4; j++)
            #pragma unroll
            for (int q = 0; q < 4; q++) oAcc[j][q] = 0.f;
        #pragma unroll
        for (int t = 0; t < 4; t++) {
            uint32_t a[4] = { pf[2*t][0], pf[2*t][1], pf[2*t+1][0], pf[2*t+1][1] };
            #pragma unroll
            for (int n16 = 0; n16 < 2; n16++) {
                uint32_t b[4];
                LDSM4T(b, sbase + ((t*16 + v_row) * AT_STRIDE + vbase + n16*16 + v_colh) * 2);
                MMA16816(oAcc[2*n16],   a, b[0], b[1]);
                MMA16816(oAcc[2*n16+1], a, b[2], b[3]);
            }
        }

        __half* orow_lo = &out[(size_t)(wi*64 + row_lo) * CC + h*32];
        __half* orow_hi = &out[(size_t)(wi*64 + row_hi) * CC + h*32];
        #pragma unroll
        for (int j = 0; j < 4; j++) {
            int col = j*8 + 2*(lane & 3);
            *(__half2*)&orow_lo[col] = __floats2half2_rn(oAcc[j][0]*ilo, oAcc[j][1]*ilo);
            *(__half2*)&orow_hi[col] = __floats2half2_rn(oAcc[j][2]*ihi, oAcc[j][3]*ihi);
        }
    }
}

// ---------------- patch-merge gather + LN(512), half out --------------------
__global__ __launch_bounds__(128) void pm_ln_kernel(
    const float* __restrict__ x, const float* __restrict__ gam,
    const float* __restrict__ bet, __half* __restrict__ out)
{
    int lane = threadIdx.x & 31;
    int warp = threadIdx.x >> 5;
    int i = blockIdx.x * 4 + warp;
    int b = i / 2304, pos = i % 2304;
    int oh = pos / 48, ow = pos % 48;
    int base = b * LL;
    int src[4];
    src[0] = base + (2*oh    ) * WW + 2*ow;
    src[1] = base + (2*oh + 1) * WW + 2*ow;
    src[2] = base + (2*oh    ) * WW + 2*ow + 1;
    src[3] = base + (2*oh + 1) * WW + 2*ow + 1;
    float4 v[4];
    float s1 = 0.f, s2 = 0.f;
    #pragma unroll
    for (int k = 0; k < 4; k++) {
        v[k] = *(const float4*)&x[(size_t)src[k] * CC + lane * 4];
        s1 += v[k].x + v[k].y + v[k].z + v[k].w;
        s2 += v[k].x*v[k].x + v[k].y*v[k].y + v[k].z*v[k].z + v[k].w*v[k].w;
    }
    #pragma unroll
    for (int o = 16; o; o >>= 1) {
        s1 += __shfl_xor_sync(0xffffffffu, s1, o);
        s2 += __shfl_xor_sync(0xffffffffu, s2, o);
    }
    float mean = s1 * (1.f / 512.f);
    float var  = s2 * (1.f / 512.f) - mean * mean;
    float rstd = rsqrtf(var + 1e-5f);
    #pragma unroll
    for (int k = 0; k < 4; k++) {
        int col = k * CC + lane * 4;
        float4 g4 = *(const float4*)&gam[col];
        float4 b4 = *(const float4*)&bet[col];
        float4 o4;
        o4.x = (v[k].x - mean) * rstd * g4.x + b4.x;
        o4.y = (v[k].y - mean) * rstd * g4.y + b4.y;
        o4.z = (v[k].z - mean) * rstd * g4.z + b4.z;
        o4.w = (v[k].w - mean) * rstd * g4.w + b4.w;
        *(uint2*)&out[(size_t)i * 512 + col] = f4_to_h4(o4);
    }
}

// ---------------- host orchestration ----------------------------------------
extern "C" void kernel_launch(void* const* d_in, const int* in_sizes, int n_in,
                              void* d_out, int out_size)
{
    (void)in_sizes; (void)n_in; (void)out_size;
    const float* x = (const float*)d_in[0];
    const float* pa[12];
    const float* pb[12];
    for (int i = 0; i < 12; i++) pa[i] = (const float*)d_in[1 + i];
    for (int i = 0; i < 12; i++) pb[i] = (const float*)d_in[13 + i];
    const float* mln_g = (const float*)d_in[25];
    const float* mln_b = (const float*)d_in[26];
    const float* red_w = (const float*)d_in[27];
    float* out = (float*)d_out;

    __half *xw, *qkv, *att, *h, *wt;
    float *xa, *xb;
    cudaGetSymbolAddress((void**)&xw,  g_xw);
    cudaGetSymbolAddress((void**)&qkv, g_qkv);
    cudaGetSymbolAddress((void**)&att, g_att);
    cudaGetSymbolAddress((void**)&xa,  g_xa);
    cudaGetSymbolAddress((void**)&xb,  g_xb);
    cudaGetSymbolAddress((void**)&h,   g_h);
    cudaGetSymbolAddress((void**)&wt,  g_wt);

    static bool attr_done = false;
    if (!attr_done) {
        cudaFuncSetAttribute(attn_mma<false>, cudaFuncAttributeMaxDynamicSharedMemorySize, AT_SMEM);
        cudaFuncSetAttribute(attn_mma<true>,  cudaFuncAttributeMaxDynamicSharedMemorySize, AT_SMEM);
        attr_done = true;
    }

    __half* a_qkv_t  = wt;
    __half* a_proj_t = wt + 49152;
    __half* a_fc1_t  = wt + 65536;
    __half* a_fc2_t  = wt + 131072;
    __half* b_qkv_t  = wt + 196608;
    __half* b_proj_t = wt + 245760;
    __half* b_fc1_t  = wt + 262144;
    __half* b_fc2_t  = wt + 327680;
    __half* red_t    = wt + 393216;

    TPJobs jb;
    jb.src[0] = pa[2];  jb.dst[0] = a_qkv_t;  jb.K[0] = 128; jb.N[0] = 384;
    jb.src[1] = pa[4];  jb.dst[1] = a_proj_t; jb.K[1] = 128; jb.N[1] = 128;
    jb.src[2] = pa[8];  jb.dst[2] = a_fc1_t;  jb.K[2] = 128; jb.N[2] = 512;
    jb.src[3] = pa[10]; jb.dst[3] = a_fc2_t;  jb.K[3] = 512; jb.N[3] = 128;
    jb.src[4] = pb[2];  jb.dst[4] = b_qkv_t;  jb.K[4] = 128; jb.N[4] = 384;
    jb.src[5] = pb[4];  jb.dst[5] = b_proj_t; jb.K[5] = 128; jb.N[5] = 128;
    jb.src[6] = pb[8];  jb.dst[6] = b_fc1_t;  jb.K[6] = 128; jb.N[6] = 512;
    jb.src[7] = pb[10]; jb.dst[7] = b_fc2_t;  jb.K[7] = 512; jb.N[7] = 128;
    jb.src[8] = red_w;  jb.dst[8] = red_t;    jb.K[8] = 512; jb.N[8] = 256;
    transpose_all<<<dim3(16, 16, 9), 256>>>(jb);

    // ---------------- block a (shift 0) ----------------
    ln_kernel<true><<<ROWS/4, 128>>>(x, pa[0], pa[1], xw, 0);
    gemm_mma<0,__half><<<dim3(ROWS/128, 3), 256, GM_SMEM>>>(xw, a_qkv_t, pa[3], qkv, nullptr, ROWS, 384, CC, 0);
    attn_mma<false><<<ROWS/NTOK, 128, AT_SMEM>>>(qkv, att);
    // proj + residual + fused LN2a -> xw
    gemm_ln<0><<<ROWS/128, 256, GM_SMEM>>>(att, a_proj_t, pa[5], xa, x, pa[6], pa[7], xw, CC, 0);
    gemm_mma<2,__half><<<dim3(ROWS/128, 4), 256, GM_SMEM>>>(xw, a_fc1_t, pa[9], h, nullptr, ROWS, 512, CC, 0);
    // fc2 + residual + fused LN1b (gather, shift 4) -> xw
    gemm_ln<1><<<ROWS/128, 256, GM_SMEM>>>(h, a_fc2_t, pa[11], xa, xa, pb[0], pb[1], xw, 512, 4);

    // ---------------- block b (shift 4) ----------------
    gemm_mma<0,__half><<<dim3(ROWS/128, 3), 256, GM_SMEM>>>(xw, b_qkv_t, pb[3], qkv, nullptr, ROWS, 384, CC, 0);
    attn_mma<true><<<ROWS/NTOK, 128, AT_SMEM>>>(qkv, att);
    // proj + residual + fused LN2b -> xw
    gemm_ln<0><<<ROWS/128, 256, GM_SMEM>>>(att, b_proj_t, pb[5], xb, xa, pb[6], pb[7], xw, CC, 4);
    gemm_mma<2,__half><<<dim3(ROWS/128, 4), 256, GM_SMEM>>>(xw, b_fc1_t, pb[9], h, nullptr, ROWS, 512, CC, 0);
    // fc2 + residual, plain
    gemm_ln<2><<<ROWS/128, 256, GM_SMEM>>>(h, b_fc2_t, pb[11], xb, xb, nullptr, nullptr, nullptr, 512, 0);

    // ---------------- patch merge ----------------
    pm_ln_kernel<<<(ROWS/4)/NTOK * 16, 128>>>(xb, mln_g, mln_b, att);
    gemm_mma<4,float><<<dim3((ROWS/4)/128, 2), 256, GM_SMEM>>>(att, red_t, nullptr, out, nullptr,
                                                               ROWS/4, 256, 512, 0);
}

// round 9
// speedup vs baseline: 2.4309x; 1.1111x over previous
#include <cuda_runtime.h>
#include <cuda_fp16.h>
#include <cstdint>

// Problem constants
#define BATCH 8
#define HH 96
#define WW 96
#define CC 128
#define LL (HH*WW)            // 9216
#define ROWS (BATCH*LL)       // 73728
#define NWIN 144
#define WS 8
#define NTOK 64
#define HEADS 4
#define HD 32
#define QKSCALE 0.17677669529663687f

// ---------------- scratch -----------------
__device__ __half g_xw [ (size_t)ROWS*CC ];
__device__ __half g_qkv[ (size_t)ROWS*3*CC ];
__device__ __half g_att[ (size_t)ROWS*CC ];
__device__ float  g_xa [ (size_t)ROWS*CC ];
__device__ float  g_xb [ (size_t)ROWS*CC ];
__device__ __half g_h  [ (size_t)ROWS*4*CC ];
__device__ __half g_wt [ 524288 ];

__device__ __forceinline__ uint32_t smem_u32(const void* p) {
    uint32_t a;
    asm("{ .reg .u64 t; cvta.to.shared.u64 t, %1; cvt.u32.u64 %0, t; }" : "=r"(a) : "l"(p));
    return a;
}
__device__ __forceinline__ float gelu_exact(float x) {
    return 0.5f * x * (1.f + erff(x * 0.70710678118654752f));
}
__device__ __forceinline__ uint2 f4_to_h4(float4 v) {
    union { uint2 u; __half2 h[2]; } cv;
    cv.h[0] = __floats2half2_rn(v.x, v.y);
    cv.h[1] = __floats2half2_rn(v.z, v.w);
    return cv.u;
}
__device__ __forceinline__ uint32_t h2pack(float a, float b) {
    union { uint32_t u; __half2 h; } cv;
    cv.h = __floats2half2_rn(a, b);
    return cv.u;
}

#define LDSM4(r, addr) \
    asm volatile("ldmatrix.sync.aligned.m8n8.x4.shared.b16 {%0,%1,%2,%3},[%4];" \
        : "=r"((r)[0]), "=r"((r)[1]), "=r"((r)[2]), "=r"((r)[3]) : "r"(addr))
#define LDSM4T(r, addr) \
    asm volatile("ldmatrix.sync.aligned.m8n8.x4.trans.shared.b16 {%0,%1,%2,%3},[%4];" \
        : "=r"((r)[0]), "=r"((r)[1]), "=r"((r)[2]), "=r"((r)[3]) : "r"(addr))
#define MMA16816(acc, a, b0, b1) \
    asm volatile("mma.sync.aligned.m16n8k16.row.col.f32.f16.f16.f32 " \
        "{%0,%1,%2,%3},{%4,%5,%6,%7},{%8,%9},{%0,%1,%2,%3};" \
        : "+f"((acc)[0]), "+f"((acc)[1]), "+f"((acc)[2]), "+f"((acc)[3]) \
        : "r"((a)[0]), "r"((a)[1]), "r"((a)[2]), "r"((a)[3]), "r"(b0), "r"(b1))

// ---------------- LayerNorm gather (block-a entry only) ----------------------
template<bool GATHER>
__global__ __launch_bounds__(128) void ln_kernel(
    const float* __restrict__ x, const float* __restrict__ gam,
    const float* __restrict__ bet, __half* __restrict__ out, int shift)
{
    int lane = threadIdx.x & 31;
    int warp = threadIdx.x >> 5;
    int r = blockIdx.x * 4 + warp;
    const float* src;
    if (GATHER) {
        int wi = r >> 6, n = r & 63;
        int b  = wi / NWIN, wl = wi % NWIN;
        int whi = wl / 12, wwi = wl % 12;
        int h0 = whi * 8 + (n >> 3), w0 = wwi * 8 + (n & 7);
        int hs = h0 + shift; if (hs >= HH) hs -= HH;
        int ws_ = w0 + shift; if (ws_ >= WW) ws_ -= WW;
        src = &x[(size_t)(b * LL + hs * WW + ws_) * CC];
    } else {
        src = &x[(size_t)r * CC];
    }
    float4 v = *(const float4*)&src[lane * 4];
    float s1 = v.x + v.y + v.z + v.w;
    float s2 = v.x*v.x + v.y*v.y + v.z*v.z + v.w*v.w;
    #pragma unroll
    for (int o = 16; o; o >>= 1) {
        s1 += __shfl_xor_sync(0xffffffffu, s1, o);
        s2 += __shfl_xor_sync(0xffffffffu, s2, o);
    }
    float mean = s1 * (1.f / CC);
    float var  = s2 * (1.f / CC) - mean * mean;
    float rstd = rsqrtf(var + 1e-5f);
    float4 g4 = *(const float4*)&gam[lane * 4];
    float4 b4 = *(const float4*)&bet[lane * 4];
    float4 o4;
    o4.x = (v.x - mean) * rstd * g4.x + b4.x;
    o4.y = (v.y - mean) * rstd * g4.y + b4.y;
    o4.z = (v.z - mean) * rstd * g4.z + b4.z;
    o4.w = (v.w - mean) * rstd * g4.w + b4.w;
    *(uint2*)&out[(size_t)r * CC + lane * 4] = f4_to_h4(o4);
}

// ---------------- batched weight transpose ----------------------------------
struct TPJobs {
    const float* src[9];
    __half* dst[9];
    int K[9];
    int N[9];
};
__global__ __launch_bounds__(256) void transpose_all(TPJobs jb)
{
    __shared__ float t[32][33];
    int m = blockIdx.z;
    int K = jb.K[m], N = jb.N[m];
    int k0 = blockIdx.x * 32, n0 = blockIdx.y * 32;
    if (k0 >= K || n0 >= N) return;
    const float* src = jb.src[m];
    __half* dst = jb.dst[m];
    int x = threadIdx.x & 31, y = threadIdx.x >> 5;
    #pragma unroll
    for (int i = 0; i < 32; i += 8)
        t[y + i][x] = src[(size_t)(k0 + y + i) * N + n0 + x];
    __syncthreads();
    #pragma unroll
    for (int i = 0; i < 32; i += 8)
        dst[(size_t)(n0 + y + i) * K + k0 + x] = __float2half_rn(t[x][y + i]);
}

// ---------------- shared GEMM plumbing (k32-chunk path) ----------------------
#define AS_STRIDE 40
#define TILE_H   (128*AS_STRIDE)
#define GM_SMEM  (4*TILE_H*2)              // 40960 bytes

__device__ __forceinline__ void copy_chunk(
    const __half* __restrict__ A, const __half* __restrict__ B,
    int bm, int bn, int K, int k0, __half* sA, __half* sB, int tid)
{
    uint32_t a_s = smem_u32(sA), b_s = smem_u32(sB);
    #pragma unroll
    for (int i = 0; i < 2; i++) {
        int idx = tid + i * 256;
        int row = idx >> 2, q = idx & 3;
        const __half* ga = &A[(size_t)(bm + row) * K + k0 + q * 8];
        const __half* gb = &B[(size_t)(bn + row) * K + k0 + q * 8];
        uint32_t so = (row * AS_STRIDE + q * 8) * 2;
        asm volatile("cp.async.cg.shared.global [%0],[%1],16;" :: "r"(a_s + so), "l"(ga));
        asm volatile("cp.async.cg.shared.global [%0],[%1],16;" :: "r"(b_s + so), "l"(gb));
    }
    asm volatile("cp.async.commit_group;" ::: "memory");
}

// ---------------- general GEMM (EPI 0:+bias | 2:+bias,GELU | 4:plain) --------
template<int EPI, typename OT>
__global__ __launch_bounds__(256)
void gemm_mma(const __half* __restrict__ A, const __half* __restrict__ B,
              const float* __restrict__ bias, OT* __restrict__ C,
              const float* __restrict__ res, int M, int N, int K, int shift)
{
    extern __shared__ __half smh[];
    __half* bufA[2] = { smh,          smh + 2*TILE_H };
    __half* bufB[2] = { smh + TILE_H, smh + 3*TILE_H };
    int tid = threadIdx.x, lane = tid & 31, wid = tid >> 5;
    int g = lane >> 2, kq = lane & 3;
    int warpM = wid & 3, warpN = wid >> 2;
    int bm = blockIdx.x * 128, bn = blockIdx.y * 128;

    float acc[2][8][4];
    #pragma unroll
    for (int i = 0; i < 2; i++)
        #pragma unroll
        for (int j = 0; j < 8; j++)
            #pragma unroll
            for (int q = 0; q < 4; q++) acc[i][j][q] = 0.f;

    int nc = K >> 5;
    copy_chunk(A, B, bm, bn, K, 0, bufA[0], bufB[0], tid);

    uint32_t a_off = (((warpM * 32 + (lane & 15)) * AS_STRIDE) + ((lane >> 4) << 3)) * 2;
    uint32_t b_off = (((warpN * 64 + (lane & 7) + (((lane >> 4) & 1) << 3)) * AS_STRIDE)
                     + (((lane >> 3) & 1) << 3)) * 2;

    for (int c = 0; c < nc; c++) {
        if (c + 1 < nc) {
            copy_chunk(A, B, bm, bn, K, (c + 1) << 5, bufA[(c+1)&1], bufB[(c+1)&1], tid);
            asm volatile("cp.async.wait_group 1;" ::: "memory");
        } else {
            asm volatile("cp.async.wait_group 0;" ::: "memory");
        }
        __syncthreads();

        uint32_t ab = smem_u32(bufA[c&1]) + a_off;
        uint32_t bb = smem_u32(bufB[c&1]) + b_off;
        #pragma unroll
        for (int ks = 0; ks < 2; ks++) {
            uint32_t a[2][4], b[4][4];
            LDSM4(a[0], ab + ks * 32);
            LDSM4(a[1], ab + 16 * AS_STRIDE * 2 + ks * 32);
            #pragma unroll
            for (int j16 = 0; j16 < 4; j16++)
                LDSM4(b[j16], bb + j16 * 16 * AS_STRIDE * 2 + ks * 32);
            #pragma unroll
            for (int i = 0; i < 2; i++)
                #pragma unroll
                for (int j = 0; j < 8; j++) {
                    uint32_t b0 = b[j >> 1][(j & 1) * 2];
                    uint32_t b1 = b[j >> 1][(j & 1) * 2 + 1];
                    MMA16816(acc[i][j], a[i], b0, b1);
                }
        }
        __syncthreads();
    }

    #pragma unroll
    for (int i = 0; i < 2; i++) {
        #pragma unroll
        for (int rr = 0; rr < 2; rr++) {
            int gr = bm + warpM * 32 + i * 16 + g + rr * 8;
            #pragma unroll
            for (int j = 0; j < 8; j++) {
                int col = bn + warpN * 64 + j * 8 + 2 * kq;
                float vx = acc[i][j][rr*2+0];
                float vy = acc[i][j][rr*2+1];
                if (EPI != 4) {
                    vx += __ldg(&bias[col]);
                    vy += __ldg(&bias[col+1]);
                }
                if (EPI == 2) { vx = gelu_exact(vx); vy = gelu_exact(vy); }
                if (sizeof(OT) == 2) {
                    *(__half2*)&((__half*)C)[(size_t)gr * N + col] = __floats2half2_rn(vx, vy);
                } else {
                    *(float2*)&((float*)C)[(size_t)gr * N + col] = make_float2(vx, vy);
                }
            }
        }
    }
}

// ---------------- wide GEMM: K=128, A resident full-K, loop over N-tiles -----
// EPI 0: +bias plain store | EPI 2: +bias + GELU
#define AW_STRIDE 136                       // 128 k-halves + 8 pad
#define AW_TILE   (128*AW_STRIDE)           // halves (17408)
#define GW_SMEM   (3*AW_TILE*2)             // A + 2 B buffers = 104448 bytes

template<int EPI>
__global__ __launch_bounds__(256)
void gemm_wide(const __half* __restrict__ A, const __half* __restrict__ B,
               const float* __restrict__ bias, __half* __restrict__ C,
               int N, int nt)
{
    extern __shared__ __half smh[];
    __half* sA = smh;
    __half* sB[2] = { smh + AW_TILE, smh + 2*AW_TILE };
    int tid = threadIdx.x, lane = tid & 31, wid = tid >> 5;
    int g = lane >> 2, kq = lane & 3;
    int warpM = wid & 3, warpN = wid >> 2;
    int bm = blockIdx.x * 128;

    // load A (full K=128) + B tile 0 as group0, B tile 1 as group1
    {
        uint32_t a_s = smem_u32(sA), b_s = smem_u32(sB[0]);
        #pragma unroll
        for (int i = 0; i < 8; i++) {
            int idx = tid + i * 256;
            int row = idx >> 4, q = idx & 15;
            uint32_t so = (row * AW_STRIDE + q * 8) * 2;
            asm volatile("cp.async.cg.shared.global [%0],[%1],16;"
                :: "r"(a_s + so), "l"(&A[(size_t)(bm + row) * 128 + q * 8]));
            asm volatile("cp.async.cg.shared.global [%0],[%1],16;"
                :: "r"(b_s + so), "l"(&B[(size_t)row * 128 + q * 8]));
        }
        asm volatile("cp.async.commit_group;" ::: "memory");
        if (nt > 1) {
            uint32_t b1_s = smem_u32(sB[1]);
            #pragma unroll
            for (int i = 0; i < 8; i++) {
                int idx = tid + i * 256;
                int row = idx >> 4, q = idx & 15;
                uint32_t so = (row * AW_STRIDE + q * 8) * 2;
                asm volatile("cp.async.cg.shared.global [%0],[%1],16;"
                    :: "r"(b1_s + so), "l"(&B[(size_t)(128 + row) * 128 + q * 8]));
            }
            asm volatile("cp.async.commit_group;" ::: "memory");
        }
    }

    uint32_t a_off = (((warpM * 32 + (lane & 15)) * AW_STRIDE) + ((lane >> 4) << 3)) * 2;
    uint32_t b_off = (((warpN * 64 + (lane & 7) + (((lane >> 4) & 1) << 3)) * AW_STRIDE)
                     + (((lane >> 3) & 1) << 3)) * 2;
    uint32_t ab = smem_u32(sA) + a_off;

    for (int bn = 0; bn < nt; bn++) {
        if (bn + 1 < nt)
            asm volatile("cp.async.wait_group 1;" ::: "memory");
        else
            asm volatile("cp.async.wait_group 0;" ::: "memory");
        __syncthreads();

        float acc[2][8][4];
        #pragma unroll
        for (int i = 0; i < 2; i++)
            #pragma unroll
            for (int j = 0; j < 8; j++)
                #pragma unroll
                for (int q = 0; q < 4; q++) acc[i][j][q] = 0.f;

        uint32_t bb = smem_u32(sB[bn & 1]) + b_off;
        #pragma unroll
        for (int ks = 0; ks < 8; ks++) {
            uint32_t a[2][4], b[4][4];
            LDSM4(a[0], ab + ks * 32);
            LDSM4(a[1], ab + 16 * AW_STRIDE * 2 + ks * 32);
            #pragma unroll
            for (int j16 = 0; j16 < 4; j16++)
                LDSM4(b[j16], bb + j16 * 16 * AW_STRIDE * 2 + ks * 32);
            #pragma unroll
            for (int i = 0; i < 2; i++)
                #pragma unroll
                for (int j = 0; j < 8; j++) {
                    uint32_t b0 = b[j >> 1][(j & 1) * 2];
                    uint32_t b1 = b[j >> 1][(j & 1) * 2 + 1];
                    MMA16816(acc[i][j], a[i], b0, b1);
                }
        }

        // epilogue for this N-tile
        #pragma unroll
        for (int i = 0; i < 2; i++) {
            #pragma unroll
            for (int rr = 0; rr < 2; rr++) {
                int gr = bm + warpM * 32 + i * 16 + g + rr * 8;
                #pragma unroll
                for (int j = 0; j < 8; j++) {
                    int col = bn * 128 + warpN * 64 + j * 8 + 2 * kq;
                    float vx = acc[i][j][rr*2+0] + __ldg(&bias[col]);
                    float vy = acc[i][j][rr*2+1] + __ldg(&bias[col+1]);
                    if (EPI == 2) { vx = gelu_exact(vx); vy = gelu_exact(vy); }
                    *(__half2*)&C[(size_t)gr * N + col] = __floats2half2_rn(vx, vy);
                }
            }
        }

        if (bn + 2 < nt) {
            __syncthreads();   // compute done before overwriting buffer bn&1
            uint32_t bs = smem_u32(sB[bn & 1]);
            #pragma unroll
            for (int i = 0; i < 8; i++) {
                int idx = tid + i * 256;
                int row = idx >> 4, q = idx & 15;
                uint32_t so = (row * AW_STRIDE + q * 8) * 2;
                asm volatile("cp.async.cg.shared.global [%0],[%1],16;"
                    :: "r"(bs + so), "l"(&B[(size_t)((bn + 2) * 128 + row) * 128 + q * 8]));
            }
            asm volatile("cp.async.commit_group;" ::: "memory");
        } else {
            __syncthreads();
        }
    }
}

// ---------------- N=128 GEMM with fused residual + LayerNorm -----------------
template<int MODE>
__global__ __launch_bounds__(256)
void gemm_ln(const __half* __restrict__ A, const __half* __restrict__ B,
             const float* __restrict__ bias, float* __restrict__ C,
             const float* __restrict__ res, const float* __restrict__ gam,
             const float* __restrict__ bet, __half* __restrict__ lnout,
             int K, int shift)
{
    extern __shared__ __half smh[];
    __half* bufA[2] = { smh,          smh + 2*TILE_H };
    __half* bufB[2] = { smh + TILE_H, smh + 3*TILE_H };
    int tid = threadIdx.x, lane = tid & 31, wid = tid >> 5;
    int g = lane >> 2, kq = lane & 3;
    int bm = blockIdx.x * 128;

    float acc[16][4];
    #pragma unroll
    for (int j = 0; j < 16; j++)
        #pragma unroll
        for (int q = 0; q < 4; q++) acc[j][q] = 0.f;

    int nc = K >> 5;
    copy_chunk(A, B, bm, 0, K, 0, bufA[0], bufB[0], tid);

    uint32_t a_off = (((wid * 16 + (lane & 15)) * AS_STRIDE) + ((lane >> 4) << 3)) * 2;
    uint32_t b_off = ((((lane & 7) + (((lane >> 4) & 1) << 3)) * AS_STRIDE)
                     + (((lane >> 3) & 1) << 3)) * 2;

    for (int c = 0; c < nc; c++) {
        if (c + 1 < nc) {
            copy_chunk(A, B, bm, 0, K, (c + 1) << 5, bufA[(c+1)&1], bufB[(c+1)&1], tid);
            asm volatile("cp.async.wait_group 1;" ::: "memory");
        } else {
            asm volatile("cp.async.wait_group 0;" ::: "memory");
        }
        __syncthreads();

        uint32_t ab = smem_u32(bufA[c&1]) + a_off;
        uint32_t bb = smem_u32(bufB[c&1]) + b_off;
        #pragma unroll
        for (int ks = 0; ks < 2; ks++) {
            uint32_t a[4];
            LDSM4(a, ab + ks * 32);
            #pragma unroll
            for (int j16 = 0; j16 < 8; j16++) {
                uint32_t b[4];
                LDSM4(b, bb + j16 * 16 * AS_STRIDE * 2 + ks * 32);
                MMA16816(acc[2*j16],   a, b[0], b[1]);
                MMA16816(acc[2*j16+1], a, b[2], b[3]);
            }
        }
        __syncthreads();
    }

    int r0 = bm + wid * 16 + g;
    int r1 = r0 + 8;
    int dst0, dst1;
    if (MODE == 0) {
        #pragma unroll
        for (int rr = 0; rr < 2; rr++) {
            int gr = rr ? r1 : r0;
            int wi = gr >> 6, n = gr & 63;
            int b  = wi / NWIN, wl = wi % NWIN;
            int whi = wl / 12, wwi = wl % 12;
            int h0 = whi * 8 + (n >> 3), w0 = wwi * 8 + (n & 7);
            int h = h0 + shift; if (h >= HH) h -= HH;
            int w = w0 + shift; if (w >= WW) w -= WW;
            int d = b * LL + h * WW + w;
            if (rr) dst1 = d; else dst0 = d;
        }
    } else {
        dst0 = r0; dst1 = r1;
    }

    float vv[16][4];
    float s1a = 0.f, s2a = 0.f, s1b = 0.f, s2b = 0.f;
    #pragma unroll
    for (int j = 0; j < 16; j++) {
        int col = j * 8 + 2 * kq;
        float bx = __ldg(&bias[col]), by = __ldg(&bias[col+1]);
        float2 ra = *(const float2*)&res[(size_t)dst0 * CC + col];
        float2 rb = *(const float2*)&res[(size_t)dst1 * CC + col];
        float v0 = acc[j][0] + bx + ra.x;
        float v1 = acc[j][1] + by + ra.y;
        float v2 = acc[j][2] + bx + rb.x;
        float v3 = acc[j][3] + by + rb.y;
        vv[j][0] = v0; vv[j][1] = v1; vv[j][2] = v2; vv[j][3] = v3;
        *(float2*)&C[(size_t)dst0 * CC + col] = make_float2(v0, v1);
        *(float2*)&C[(size_t)dst1 * CC + col] = make_float2(v2, v3);
        if (MODE != 2) {
            s1a += v0 + v1; s2a += v0*v0 + v1*v1;
            s1b += v2 + v3; s2b += v2*v2 + v3*v3;
        }
    }
    if (MODE == 2) return;

    s1a += __shfl_xor_sync(0xffffffffu, s1a, 1);
    s1a += __shfl_xor_sync(0xffffffffu, s1a, 2);
    s2a += __shfl_xor_sync(0xffffffffu, s2a, 1);
    s2a += __shfl_xor_sync(0xffffffffu, s2a, 2);
    s1b += __shfl_xor_sync(0xffffffffu, s1b, 1);
    s1b += __shfl_xor_sync(0xffffffffu, s1b, 2);
    s2b += __shfl_xor_sync(0xffffffffu, s2b, 1);
    s2b += __shfl_xor_sync(0xffffffffu, s2b, 2);

    float ma = s1a * (1.f/CC), va = s2a * (1.f/CC) - ma*ma;
    float mb = s1b * (1.f/CC), vb = s2b * (1.f/CC) - mb*mb;
    float ra_ = rsqrtf(va + 1e-5f), rb_ = rsqrtf(vb + 1e-5f);

    int ln0, ln1;
    if (MODE == 0) { ln0 = dst0; ln1 = dst1; }
    else {
        #pragma unroll
        for (int rr = 0; rr < 2; rr++) {
            int gr = rr ? r1 : r0;
            int b = gr / LL, rem = gr % LL;
            int h = rem / WW, w = rem % WW;
            int h0 = h - 4; if (h0 < 0) h0 += HH;
            int w0 = w - 4; if (w0 < 0) w0 += WW;
            int r = b * LL + ((h0 >> 3) * 12 + (w0 >> 3)) * 64 + (h0 & 7) * 8 + (w0 & 7);
            if (rr) ln1 = r; else ln0 = r;
        }
    }

    #pragma unroll
    for (int j = 0; j < 16; j++) {
        int col = j * 8 + 2 * kq;
        float gx = __ldg(&gam[col]), gy = __ldg(&gam[col+1]);
        float bx = __ldg(&bet[col]), by = __ldg(&bet[col+1]);
        *(__half2*)&lnout[(size_t)ln0 * CC + col] =
            __floats2half2_rn((vv[j][0]-ma)*ra_*gx+bx, (vv[j][1]-ma)*ra_*gy+by);
        *(__half2*)&lnout[(size_t)ln1 * CC + col] =
            __floats2half2_rn((vv[j][2]-mb)*rb_*gx+bx, (vv[j][3]-mb)*rb_*gy+by);
    }
}

// ---------------- MMA windowed attention (conflict-free stride 392) ----------
#define AT_STRIDE 392
#define AT_SMEM   (64*AT_STRIDE*2 + 64*4)   // 50432 bytes

template<bool SHIFTED>
__global__ __launch_bounds__(128) void attn_mma(
    const __half* __restrict__ qkv, __half* __restrict__ out)
{
    extern __shared__ __half smw[];
    int* lab = (int*)(smw + 64*AT_STRIDE);
    int tid = threadIdx.x, lane = tid & 31, h = tid >> 5;
    int wi = blockIdx.x;

    const uint4* gsrc = (const uint4*)(qkv + (size_t)wi * 64 * 384);
    #pragma unroll
    for (int i = 0; i < 24; i++) {
        int idx = tid + i * 128;
        int row = idx / 48, seg = idx % 48;
        *(uint4*)&smw[row * AT_STRIDE + seg * 8] = gsrc[row * 48 + seg];
    }
    if (SHIFTED && tid < 64) {
        int wl = wi % NWIN;
        int whi = wl / 12, wwi = wl % 12;
        int hh = whi * 8 + (tid >> 3), ww_ = wwi * 8 + (tid & 7);
        int hr = (hh < HH - WS) ? 0 : ((hh < HH - 4) ? 1 : 2);
        int wr = (ww_ < WW - WS) ? 0 : ((ww_ < WW - 4) ? 1 : 2);
        lab[tid] = hr * 3 + wr;
    }
    __syncthreads();

    uint32_t sbase = smem_u32(smw);
    int qbase = h * 32;
    int kbase = 128 + h * 32;
    int vbase = 256 + h * 32;

    uint32_t q_row  = lane & 15;
    uint32_t q_colh = (lane >> 4) << 3;
    uint32_t k_row  = (lane & 7) + (((lane >> 4) & 1) << 3);
    uint32_t k_colh = ((lane >> 3) & 1) << 3;
    uint32_t v_row  = lane & 15;
    uint32_t v_colh = (lane >> 4) << 3;

    #pragma unroll
    for (int mt = 0; mt < 4; mt++) {
        float sAcc[8][4];
        #pragma unroll
        for (int j = 0; j < 8; j++)
            #pragma unroll
            for (int q = 0; q < 4; q++) sAcc[j][q] = 0.f;
        #pragma unroll
        for (int kt = 0; kt < 2; kt++) {
            uint32_t a[4];
            LDSM4(a, sbase + ((mt*16 + q_row) * AT_STRIDE + qbase + q_colh + kt*16) * 2);
            #pragma unroll
            for (int j16 = 0; j16 < 4; j16++) {
                uint32_t b[4];
                LDSM4(b, sbase + ((j16*16 + k_row) * AT_STRIDE + kbase + k_colh + kt*16) * 2);
                MMA16816(sAcc[2*j16],   a, b[0], b[1]);
                MMA16816(sAcc[2*j16+1], a, b[2], b[3]);
            }
        }

        int row_lo = mt*16 + (lane >> 2);
        int row_hi = row_lo + 8;
        if (SHIFTED) {
            int ll = lab[row_lo], lh = lab[row_hi];
            #pragma unroll
            for (int j = 0; j < 8; j++) {
                int c0 = j*8 + 2*(lane & 3);
                int lc0 = lab[c0], lc1 = lab[c0+1];
                if (lc0 != ll) sAcc[j][0] = -1e30f;
                if (lc1 != ll) sAcc[j][1] = -1e30f;
                if (lc0 != lh) sAcc[j][2] = -1e30f;
                if (lc1 != lh) sAcc[j][3] = -1e30f;
            }
        }
        float mlo = -1e30f, mhi = -1e30f;
        #pragma unroll
        for (int j = 0; j < 8; j++) {
            mlo = fmaxf(mlo, fmaxf(sAcc[j][0], sAcc[j][1]));
            mhi = fmaxf(mhi, fmaxf(sAcc[j][2], sAcc[j][3]));
        }
        mlo = fmaxf(mlo, __shfl_xor_sync(0xffffffffu, mlo, 1));
        mlo = fmaxf(mlo, __shfl_xor_sync(0xffffffffu, mlo, 2));
        mhi = fmaxf(mhi, __shfl_xor_sync(0xffffffffu, mhi, 1));
        mhi = fmaxf(mhi, __shfl_xor_sync(0xffffffffu, mhi, 2));
        float slo = 0.f, shi = 0.f;
        uint32_t pf[8][2];
        #pragma unroll
        for (int j = 0; j < 8; j++) {
            float e0 = __expf((sAcc[j][0] - mlo) * QKSCALE);
            float e1 = __expf((sAcc[j][1] - mlo) * QKSCALE);
            float e2 = __expf((sAcc[j][2] - mhi) * QKSCALE);
            float e3 = __expf((sAcc[j][3] - mhi) * QKSCALE);
            slo += e0 + e1; shi += e2 + e3;
            pf[j][0] = h2pack(e0, e1);
            pf[j][1] = h2pack(e2, e3);
        }
        slo += __shfl_xor_sync(0xffffffffu, slo, 1);
        slo += __shfl_xor_sync(0xffffffffu, slo, 2);
        shi += __shfl_xor_sync(0xffffffffu, shi, 1);
        shi += __shfl_xor_sync(0xffffffffu, shi, 2);
        float ilo = 1.f / slo, ihi = 1.f / shi;

        float oAcc[4][4];
        #pragma unroll
        for (int j = 0; j < 4; j++)
            #pragma unroll
            for (int q = 0; q < 4; q++) oAcc[j][q] = 0.f;
        #pragma unroll
        for (int t = 0; t < 4; t++) {
            uint32_t a[4] = { pf[2*t][0], pf[2*t][1], pf[2*t+1][0], pf[2*t+1][1] };
            #pragma unroll
            for (int n16 = 0; n16 < 2; n16++) {
                uint32_t b[4];
                LDSM4T(b, sbase + ((t*16 + v_row) * AT_STRIDE + vbase + n16*16 + v_colh) * 2);
                MMA16816(oAcc[2*n16],   a, b[0], b[1]);
                MMA16816(oAcc[2*n16+1], a, b[2], b[3]);
            }
        }

        __half* orow_lo = &out[(size_t)(wi*64 + row_lo) * CC + h*32];
        __half* orow_hi = &out[(size_t)(wi*64 + row_hi) * CC + h*32];
        #pragma unroll
        for (int j = 0; j < 4; j++) {
            int col = j*8 + 2*(lane & 3);
            *(__half2*)&orow_lo[col] = __floats2half2_rn(oAcc[j][0]*ilo, oAcc[j][1]*ilo);
            *(__half2*)&orow_hi[col] = __floats2half2_rn(oAcc[j][2]*ihi, oAcc[j][3]*ihi);
        }
    }
}

// ---------------- patch-merge gather + LN(512), half out --------------------
__global__ __launch_bounds__(128) void pm_ln_kernel(
    const float* __restrict__ x, const float* __restrict__ gam,
    const float* __restrict__ bet, __half* __restrict__ out)
{
    int lane = threadIdx.x & 31;
    int warp = threadIdx.x >> 5;
    int i = blockIdx.x * 4 + warp;
    int b = i / 2304, pos = i % 2304;
    int oh = pos / 48, ow = pos % 48;
    int base = b * LL;
    int src[4];
    src[0] = base + (2*oh    ) * WW + 2*ow;
    src[1] = base + (2*oh + 1) * WW + 2*ow;
    src[2] = base + (2*oh    ) * WW + 2*ow + 1;
    src[3] = base + (2*oh + 1) * WW + 2*ow + 1;
    float4 v[4];
    float s1 = 0.f, s2 = 0.f;
    #pragma unroll
    for (int k = 0; k < 4; k++) {
        v[k] = *(const float4*)&x[(size_t)src[k] * CC + lane * 4];
        s1 += v[k].x + v[k].y + v[k].z + v[k].w;
        s2 += v[k].x*v[k].x + v[k].y*v[k].y + v[k].z*v[k].z + v[k].w*v[k].w;
    }
    #pragma unroll
    for (int o = 16; o; o >>= 1) {
        s1 += __shfl_xor_sync(0xffffffffu, s1, o);
        s2 += __shfl_xor_sync(0xffffffffu, s2, o);
    }
    float mean = s1 * (1.f / 512.f);
    float var  = s2 * (1.f / 512.f) - mean * mean;
    float rstd = rsqrtf(var + 1e-5f);
    #pragma unroll
    for (int k = 0; k < 4; k++) {
        int col = k * CC + lane * 4;
        float4 g4 = *(const float4*)&gam[col];
        float4 b4 = *(const float4*)&bet[col];
        float4 o4;
        o4.x = (v[k].x - mean) * rstd * g4.x + b4.x;
        o4.y = (v[k].y - mean) * rstd * g4.y + b4.y;
        o4.z = (v[k].z - mean) * rstd * g4.z + b4.z;
        o4.w = (v[k].w - mean) * rstd * g4.w + b4.w;
        *(uint2*)&out[(size_t)i * 512 + col] = f4_to_h4(o4);
    }
}

// ---------------- host orchestration ----------------------------------------
extern "C" void kernel_launch(void* const* d_in, const int* in_sizes, int n_in,
                              void* d_out, int out_size)
{
    (void)in_sizes; (void)n_in; (void)out_size;
    const float* x = (const float*)d_in[0];
    const float* pa[12];
    const float* pb[12];
    for (int i = 0; i < 12; i++) pa[i] = (const float*)d_in[1 + i];
    for (int i = 0; i < 12; i++) pb[i] = (const float*)d_in[13 + i];
    const float* mln_g = (const float*)d_in[25];
    const float* mln_b = (const float*)d_in[26];
    const float* red_w = (const float*)d_in[27];
    float* out = (float*)d_out;

    __half *xw, *qkv, *att, *h, *wt;
    float *xa, *xb;
    cudaGetSymbolAddress((void**)&xw,  g_xw);
    cudaGetSymbolAddress((void**)&qkv, g_qkv);
    cudaGetSymbolAddress((void**)&att, g_att);
    cudaGetSymbolAddress((void**)&xa,  g_xa);
    cudaGetSymbolAddress((void**)&xb,  g_xb);
    cudaGetSymbolAddress((void**)&h,   g_h);
    cudaGetSymbolAddress((void**)&wt,  g_wt);

    static bool attr_done = false;
    if (!attr_done) {
        cudaFuncSetAttribute(attn_mma<false>, cudaFuncAttributeMaxDynamicSharedMemorySize, AT_SMEM);
        cudaFuncSetAttribute(attn_mma<true>,  cudaFuncAttributeMaxDynamicSharedMemorySize, AT_SMEM);
        cudaFuncSetAttribute(gemm_wide<0>, cudaFuncAttributeMaxDynamicSharedMemorySize, GW_SMEM);
        cudaFuncSetAttribute(gemm_wide<2>, cudaFuncAttributeMaxDynamicSharedMemorySize, GW_SMEM);
        attr_done = true;
    }

    __half* a_qkv_t  = wt;
    __half* a_proj_t = wt + 49152;
    __half* a_fc1_t  = wt + 65536;
    __half* a_fc2_t  = wt + 131072;
    __half* b_qkv_t  = wt + 196608;
    __half* b_proj_t = wt + 245760;
    __half* b_fc1_t  = wt + 262144;
    __half* b_fc2_t  = wt + 327680;
    __half* red_t    = wt + 393216;

    TPJobs jb;
    jb.src[0] = pa[2];  jb.dst[0] = a_qkv_t;  jb.K[0] = 128; jb.N[0] = 384;
    jb.src[1] = pa[4];  jb.dst[1] = a_proj_t; jb.K[1] = 128; jb.N[1] = 128;
    jb.src[2] = pa[8];  jb.dst[2] = a_fc1_t;  jb.K[2] = 128; jb.N[2] = 512;
    jb.src[3] = pa[10]; jb.dst[3] = a_fc2_t;  jb.K[3] = 512; jb.N[3] = 128;
    jb.src[4] = pb[2];  jb.dst[4] = b_qkv_t;  jb.K[4] = 128; jb.N[4] = 384;
    jb.src[5] = pb[4];  jb.dst[5] = b_proj_t; jb.K[5] = 128; jb.N[5] = 128;
    jb.src[6] = pb[8];  jb.dst[6] = b_fc1_t;  jb.K[6] = 128; jb.N[6] = 512;
    jb.src[7] = pb[10]; jb.dst[7] = b_fc2_t;  jb.K[7] = 512; jb.N[7] = 128;
    jb.src[8] = red_w;  jb.dst[8] = red_t;    jb.K[8] = 512; jb.N[8] = 256;
    transpose_all<<<dim3(16, 16, 9), 256>>>(jb);

    // ---------------- block a (shift 0) ----------------
    ln_kernel<true><<<ROWS/4, 128>>>(x, pa[0], pa[1], xw, 0);
    gemm_wide<0><<<ROWS/128, 256, GW_SMEM>>>(xw, a_qkv_t, pa[3], qkv, 384, 3);
    attn_mma<false><<<ROWS/NTOK, 128, AT_SMEM>>>(qkv, att);
    gemm_ln<0><<<ROWS/128, 256, GM_SMEM>>>(att, a_proj_t, pa[5], xa, x, pa[6], pa[7], xw, CC, 0);
    gemm_wide<2><<<ROWS/128, 256, GW_SMEM>>>(xw, a_fc1_t, pa[9], h, 512, 4);
    gemm_ln<1><<<ROWS/128, 256, GM_SMEM>>>(h, a_fc2_t, pa[11], xa, xa, pb[0], pb[1], xw, 512, 4);

    // ---------------- block b (shift 4) ----------------
    gemm_wide<0><<<ROWS/128, 256, GW_SMEM>>>(xw, b_qkv_t, pb[3], qkv, 384, 3);
    attn_mma<true><<<ROWS/NTOK, 128, AT_SMEM>>>(qkv, att);
    gemm_ln<0><<<ROWS/128, 256, GM_SMEM>>>(att, b_proj_t, pb[5], xb, xa, pb[6], pb[7], xw, CC, 4);
    gemm_wide<2><<<ROWS/128, 256, GW_SMEM>>>(xw, b_fc1_t, pb[9], h, 512, 4);
    gemm_ln<2><<<ROWS/128, 256, GM_SMEM>>>(h, b_fc2_t, pb[11], xb, xb, nullptr, nullptr, nullptr, 512, 0);

    // ---------------- patch merge ----------------
    pm_ln_kernel<<<(ROWS/4)/NTOK * 16, 128>>>(xb, mln_g, mln_b, att);
    gemm_mma<4,float><<<dim3((ROWS/4)/128, 2), 256, GM_SMEM>>>(att, red_t, nullptr, out, nullptr,
                                                               ROWS/4, 256, 512, 0);
}